// round 2
// baseline (speedup 1.0000x reference)
#include <cuda_runtime.h>
#include <cuda_bf16.h>

#define NMAX 50000
#define EMAX 800000

// Scratch (device globals; no allocation allowed)
__device__ __align__(16) float g_bufA[NMAX * 88];
__device__ __align__(16) float g_bufB[NMAX * 88];
__device__ __align__(16) float g_t[NMAX * 88];
__device__ float g_deg[NMAX];      // degree, then overwritten by dis = rsqrt(deg)
__device__ float g_norm[EMAX];
__device__ float g_stats[256];     // [0..FO) sum, [128..128+FO) sumsq

// ---------------- prologue kernels ----------------

__global__ void deg_init_kernel(float* deg, int n) {
    int i = blockIdx.x * blockDim.x + threadIdx.x;
    if (i < n) deg[i] = 1.0f;  // self-loop contribution
}

__global__ void deg_edges_kernel(const int* __restrict__ dst, float* deg, int E) {
    int e = blockIdx.x * blockDim.x + threadIdx.x;
    if (e < E) atomicAdd(&deg[dst[e]], 1.0f);
}

__global__ void dis_kernel(float* deg, int n) {
    int i = blockIdx.x * blockDim.x + threadIdx.x;
    if (i < n) deg[i] = rsqrtf(deg[i]);  // deg >= 1 always
}

__global__ void norm_kernel(const int* __restrict__ src,
                            const int* __restrict__ dst,
                            const float* __restrict__ dis,
                            float* __restrict__ norm, int E) {
    int e = blockIdx.x * blockDim.x + threadIdx.x;
    if (e < E) norm[e] = dis[src[e]] * dis[dst[e]];
}

// ---------------- per-layer kernels (templated on dims) ----------------

template <int FI, int FO>
__global__ void gemm_kernel(const float* __restrict__ x, const float* __restrict__ W,
                            float* __restrict__ t, int n) {
    __shared__ float sW[FI * FO];
    for (int i = threadIdx.x; i < FI * FO; i += blockDim.x) sW[i] = W[i];
    __syncthreads();
    int idx = blockIdx.x * blockDim.x + threadIdx.x;
    if (idx >= n * FO) return;
    int row = idx / FO;
    int col = idx - row * FO;
    const float* xr = x + row * FI;
    float acc = 0.0f;
#pragma unroll
    for (int k = 0; k < FI; k++) acc += __ldg(&xr[k]) * sW[k * FO + col];
    t[idx] = acc;
}

// out[i,c] = t[i,c] * dis[i]^2 (self-loop) + b[c]
template <int FO>
__global__ void init_out_kernel(const float* __restrict__ t, const float* __restrict__ dis,
                                const float* __restrict__ b, float* __restrict__ out, int n) {
    int idx = blockIdx.x * blockDim.x + threadIdx.x;
    if (idx >= n * FO) return;
    int row = idx / FO;
    int col = idx - row * FO;
    float d = dis[row];
    out[idx] = t[idx] * d * d + b[col];
}

// one thread per (edge, channel-pair)
template <int FO>
__global__ void agg_edges_kernel(const int* __restrict__ src,
                                 const int* __restrict__ dst,
                                 const float* __restrict__ norm,
                                 const float* __restrict__ t,
                                 float* __restrict__ out, int E) {
    constexpr int NC = FO / 2;
    int idx = blockIdx.x * blockDim.x + threadIdx.x;
    if (idx >= E * NC) return;
    int e = idx / NC;
    int c = idx - e * NC;
    int s = src[e];
    int d = dst[e];
    float nm = norm[e];
    float2 v = *reinterpret_cast<const float2*>(t + s * FO + 2 * c);
    float* o = out + d * FO + 2 * c;
    atomicAdd(o,     v.x * nm);
    atomicAdd(o + 1, v.y * nm);
}

__global__ void zero_stats_kernel(float* stats) {
    stats[threadIdx.x] = 0.0f;  // 256 threads, 1 block
}

// in-place ReLU + per-channel sum / sumsq (block partials -> global atomics)
template <int FO>
__global__ void relu_stats_kernel(float* __restrict__ out, float* __restrict__ stats, int n) {
    __shared__ float ssum[FO];
    __shared__ float ssq[FO];
    for (int i = threadIdx.x; i < FO; i += blockDim.x) { ssum[i] = 0.0f; ssq[i] = 0.0f; }
    __syncthreads();
    int total = n * FO;
    int start = blockIdx.x * 4096 + threadIdx.x;
    int end = min(blockIdx.x * 4096 + 4096, total);
    for (int i = start; i < end; i += 256) {
        float v = out[i];
        v = fmaxf(v, 0.0f);
        out[i] = v;
        int c = i % FO;
        atomicAdd(&ssum[c], v);
        atomicAdd(&ssq[c], v * v);
    }
    __syncthreads();
    for (int c = threadIdx.x; c < FO; c += blockDim.x) {
        atomicAdd(&stats[c], ssum[c]);
        atomicAdd(&stats[128 + c], ssq[c]);
    }
}

template <int FO>
__global__ void bn_apply_kernel(float* __restrict__ out, const float* __restrict__ stats,
                                const float* __restrict__ g, const float* __restrict__ be,
                                int n) {
    int idx = blockIdx.x * blockDim.x + threadIdx.x;
    if (idx >= n * FO) return;
    int c = idx % FO;
    float inv_n = 1.0f / (float)n;
    float mu = stats[c] * inv_n;
    float var = stats[128 + c] * inv_n - mu * mu;
    float sc = g[c] * rsqrtf(var + 1e-5f);
    out[idx] = sc * (out[idx] - mu) + be[c];
}

// ---------------- host-side layer driver ----------------

template <int FI, int FO>
static void run_layer(const float* in, const float* W, const float* b,
                      float* t, float* out,
                      const int* src, const int* dst,
                      const float* norm, const float* dis,
                      int n, int E,
                      const float* g, const float* be, float* stats) {
    int tot = n * FO;
    gemm_kernel<FI, FO><<<(tot + 255) / 256, 256>>>(in, W, t, n);
    init_out_kernel<FO><<<(tot + 255) / 256, 256>>>(t, dis, b, out, n);
    int etot = E * (FO / 2);
    agg_edges_kernel<FO><<<(etot + 255) / 256, 256>>>(src, dst, norm, t, out, E);
    if (g != nullptr) {
        zero_stats_kernel<<<1, 256>>>(stats);
        relu_stats_kernel<FO><<<(tot + 4095) / 4096, 256>>>(out, stats, n);
        bn_apply_kernel<FO><<<(tot + 255) / 256, 256>>>(out, stats, g, be, n);
    }
}

extern "C" void kernel_launch(void* const* d_in, const int* in_sizes, int n_in,
                              void* d_out, int out_size) {
    const float* x = (const float*)d_in[0];
    const int* edge = (const int*)d_in[1];   // JAX default x64-disabled: int32
    const float* W1 = (const float*)d_in[2];
    const float* b1 = (const float*)d_in[3];
    const float* W2 = (const float*)d_in[4];
    const float* b2 = (const float*)d_in[5];
    const float* W3 = (const float*)d_in[6];
    const float* b3 = (const float*)d_in[7];
    const float* W4 = (const float*)d_in[8];
    const float* b4 = (const float*)d_in[9];
    const float* W5 = (const float*)d_in[10];
    const float* b5 = (const float*)d_in[11];
    const float* W6 = (const float*)d_in[12];
    const float* b6 = (const float*)d_in[13];
    const float* g1 = (const float*)d_in[14];
    const float* be1 = (const float*)d_in[15];
    const float* g2 = (const float*)d_in[16];
    const float* be2 = (const float*)d_in[17];
    const float* g3 = (const float*)d_in[18];
    const float* be3 = (const float*)d_in[19];
    const float* g4 = (const float*)d_in[20];
    const float* be4 = (const float*)d_in[21];

    int n = in_sizes[0] / 88;
    int E = in_sizes[1] / 2;
    const int* src = edge;
    const int* dst = edge + E;

    float *bufA, *bufB, *t, *deg, *norm, *stats;
    cudaGetSymbolAddress((void**)&bufA, g_bufA);
    cudaGetSymbolAddress((void**)&bufB, g_bufB);
    cudaGetSymbolAddress((void**)&t, g_t);
    cudaGetSymbolAddress((void**)&deg, g_deg);
    cudaGetSymbolAddress((void**)&norm, g_norm);
    cudaGetSymbolAddress((void**)&stats, g_stats);

    float* out = (float*)d_out;

    // prologue: degrees (with self-loops), dis = rsqrt(deg), per-edge norm
    deg_init_kernel<<<(n + 255) / 256, 256>>>(deg, n);
    deg_edges_kernel<<<(E + 255) / 256, 256>>>(dst, deg, E);
    dis_kernel<<<(n + 255) / 256, 256>>>(deg, n);   // deg now holds dis
    norm_kernel<<<(E + 255) / 256, 256>>>(src, dst, deg, norm, E);
    const float* dis = deg;

    // encoder
    run_layer<88, 70>(x,    W1, b1, t, bufA, src, dst, norm, dis, n, E, g1, be1, stats);
    run_layer<70, 60>(bufA, W2, b2, t, bufB, src, dst, norm, dis, n, E, g2, be2, stats);
    run_layer<60, 50>(bufB, W3, b3, t, bufA, src, dst, norm, dis, n, E, nullptr, nullptr, stats);
    // decoder
    run_layer<50, 60>(bufA, W4, b4, t, bufB, src, dst, norm, dis, n, E, g3, be3, stats);
    run_layer<60, 70>(bufB, W5, b5, t, bufA, src, dst, norm, dis, n, E, g4, be4, stats);
    run_layer<70, 88>(bufA, W6, b6, t, out,  src, dst, norm, dis, n, E, nullptr, nullptr, stats);
}

// round 3
// speedup vs baseline: 1.2180x; 1.2180x over previous
#include <cuda_runtime.h>
#include <cuda_bf16.h>

#define NMAX 50000
#define EMAX 800000

// ---- scratch (device globals; no allocation allowed) ----
__device__ __align__(16) float g_bufA[NMAX * 88];
__device__ __align__(16) float g_bufB[NMAX * 88];
__device__ __align__(16) float g_t[NMAX * 88];
__device__ float g_dis[NMAX];
__device__ int   g_counts[NMAX];
__device__ int   g_rowptr[NMAX + 1];
__device__ int   g_cursor[NMAX];
__device__ int   g_csr_src[EMAX];
__device__ float g_csr_w[EMAX];
__device__ float g_stats[256];   // [0..FO) sum, [128..128+FO) sumsq
__device__ float g_sc[128];      // bn scale per channel
__device__ float g_sh[128];      // bn shift per channel

// ---------------- CSR build ----------------

__global__ void zero_counts_kernel(int* counts, int n) {
    int i = blockIdx.x * blockDim.x + threadIdx.x;
    if (i < n) counts[i] = 0;
}

__global__ void count_kernel(const int* __restrict__ dst, int* counts, int E) {
    int e = blockIdx.x * blockDim.x + threadIdx.x;
    if (e < E) atomicAdd(&counts[dst[e]], 1);
}

// single block, 1024 threads: exclusive scan of counts -> row_ptr, cursor; dis = rsqrt(deg+1)
__global__ void scan_kernel(const int* __restrict__ counts, int* __restrict__ row_ptr,
                            int* __restrict__ cursor, float* __restrict__ dis, int n) {
    __shared__ int part[1024];
    int tid = threadIdx.x;
    int chunk = (n + 1023) / 1024;
    int beg = tid * chunk;
    int end = min(beg + chunk, n);
    int s = 0;
    for (int i = beg; i < end; i++) s += counts[i];
    part[tid] = s;
    __syncthreads();
    // Hillis-Steele inclusive scan
    for (int off = 1; off < 1024; off <<= 1) {
        int v = part[tid];
        int add = (tid >= off) ? part[tid - off] : 0;
        __syncthreads();
        part[tid] = v + add;
        __syncthreads();
    }
    int run = (tid > 0) ? part[tid - 1] : 0;
    for (int i = beg; i < end; i++) {
        int c = counts[i];
        row_ptr[i] = run;
        cursor[i] = run;
        dis[i] = rsqrtf((float)c + 1.0f);
        run += c;
    }
    if (tid == 1023) row_ptr[n] = part[1023];
}

__global__ void scatter_kernel(const int* __restrict__ src, const int* __restrict__ dst,
                               const float* __restrict__ dis,
                               int* __restrict__ cursor,
                               int* __restrict__ csr_src, float* __restrict__ csr_w, int E) {
    int e = blockIdx.x * blockDim.x + threadIdx.x;
    if (e >= E) return;
    int s = src[e];
    int d = dst[e];
    int pos = atomicAdd(&cursor[d], 1);
    csr_src[pos] = s;
    csr_w[pos] = dis[s] * dis[d];
}

// ---------------- GEMM (optionally applies BN affine to input; optionally zeroes stats) ----------------

template <int FI, int FO, bool AFFINE, bool ZERO_STATS>
__global__ void gemm_kernel(const float* __restrict__ x, const float* __restrict__ W,
                            const float* __restrict__ sc, const float* __restrict__ sh,
                            float* __restrict__ t, float* __restrict__ stats, int n) {
    __shared__ float sW[FI * FO];
    __shared__ float s_sc[FI], s_sh[FI];
    for (int i = threadIdx.x; i < FI * FO; i += blockDim.x) sW[i] = W[i];
    if (AFFINE) {
        for (int i = threadIdx.x; i < FI; i += blockDim.x) { s_sc[i] = sc[i]; s_sh[i] = sh[i]; }
    }
    if (ZERO_STATS && blockIdx.x == 0 && threadIdx.x < 256) stats[threadIdx.x] = 0.0f;
    __syncthreads();
    int idx = blockIdx.x * blockDim.x + threadIdx.x;
    if (idx >= n * FO) return;
    int row = idx / FO;
    int col = idx - row * FO;
    const float* xr = x + row * FI;
    float acc = 0.0f;
#pragma unroll
    for (int k = 0; k < FI; k++) {
        float v = __ldg(&xr[k]);
        if (AFFINE) v = v * s_sc[k] + s_sh[k];
        acc += v * sW[k * FO + col];
    }
    t[idx] = acc;
}

// ---------------- CSR aggregation: one warp per node, fused self-loop+bias(+relu+stats) ----------------

template <int FO, bool RELU_STATS>
__global__ void agg_csr_kernel(const int* __restrict__ rp, const int* __restrict__ ci,
                               const float* __restrict__ cw,
                               const float* __restrict__ t, const float* __restrict__ dis,
                               const float* __restrict__ b,
                               float* __restrict__ out, float* __restrict__ stats, int n) {
    constexpr int K = (FO + 31) / 32;
    __shared__ float ssum[RELU_STATS ? FO : 1];
    __shared__ float ssq[RELU_STATS ? FO : 1];
    if (RELU_STATS) {
        for (int i = threadIdx.x; i < FO; i += blockDim.x) { ssum[i] = 0.0f; ssq[i] = 0.0f; }
        __syncthreads();
    }
    int lane = threadIdx.x & 31;
    int warp = (blockIdx.x * blockDim.x + threadIdx.x) >> 5;
    int nwarps = (gridDim.x * blockDim.x) >> 5;

    int c[K];
    bool act[K];
    float bias[K];
    float psum[K], psq[K];
#pragma unroll
    for (int k = 0; k < K; k++) {
        c[k] = k * 32 + lane;
        act[k] = (c[k] < FO);
        bias[k] = act[k] ? __ldg(&b[c[k]]) : 0.0f;
        psum[k] = 0.0f;
        psq[k] = 0.0f;
    }

    for (int i = warp; i < n; i += nwarps) {
        float d = dis[i];
        float d2 = d * d;
        float acc[K];
#pragma unroll
        for (int k = 0; k < K; k++)
            acc[k] = act[k] ? (t[i * FO + c[k]] * d2 + bias[k]) : 0.0f;

        int beg = rp[i], end = rp[i + 1];
        int j = beg;
        for (; j + 1 < end; j += 2) {
            int s0 = ci[j], s1 = ci[j + 1];
            float w0 = cw[j], w1 = cw[j + 1];
#pragma unroll
            for (int k = 0; k < K; k++) {
                if (act[k]) {
                    acc[k] += t[s0 * FO + c[k]] * w0;
                    acc[k] += t[s1 * FO + c[k]] * w1;
                }
            }
        }
        if (j < end) {
            int s0 = ci[j];
            float w0 = cw[j];
#pragma unroll
            for (int k = 0; k < K; k++)
                if (act[k]) acc[k] += t[s0 * FO + c[k]] * w0;
        }

#pragma unroll
        for (int k = 0; k < K; k++) {
            if (!act[k]) continue;
            float v = acc[k];
            if (RELU_STATS) {
                v = fmaxf(v, 0.0f);
                psum[k] += v;
                psq[k] += v * v;
            }
            out[i * FO + c[k]] = v;
        }
    }

    if (RELU_STATS) {
#pragma unroll
        for (int k = 0; k < K; k++) {
            if (act[k]) {
                atomicAdd(&ssum[c[k]], psum[k]);
                atomicAdd(&ssq[c[k]], psq[k]);
            }
        }
        __syncthreads();
        for (int i = threadIdx.x; i < FO; i += blockDim.x) {
            atomicAdd(&stats[i], ssum[i]);
            atomicAdd(&stats[128 + i], ssq[i]);
        }
    }
}

// ---------------- BN finalize: sc/sh per channel ----------------

template <int FO>
__global__ void bn_finalize_kernel(const float* __restrict__ stats,
                                   const float* __restrict__ g, const float* __restrict__ be,
                                   float* __restrict__ sc, float* __restrict__ sh, int n) {
    int c = threadIdx.x;
    if (c >= FO) return;
    float inv_n = 1.0f / (float)n;
    float mu = stats[c] * inv_n;
    float var = stats[128 + c] * inv_n - mu * mu;
    float s = g[c] * rsqrtf(var + 1e-5f);
    sc[c] = s;
    sh[c] = be[c] - mu * s;
}

// ---------------- host driver ----------------

template <int FI, int FO, bool AFFINE, bool BN>
static void run_layer(const float* in, const float* W, const float* b,
                      float* t, float* out,
                      const int* rp, const int* ci, const float* cw,
                      const float* dis, int n,
                      const float* g, const float* be,
                      float* stats, float* sc, float* sh) {
    int tot = n * FO;
    gemm_kernel<FI, FO, AFFINE, BN><<<(tot + 255) / 256, 256>>>(in, W, sc, sh, t, stats, n);
    agg_csr_kernel<FO, BN><<<1024, 256>>>(rp, ci, cw, t, dis, b, out, stats, n);
    if (BN) bn_finalize_kernel<FO><<<1, 128>>>(stats, g, be, sc, sh, n);
}

extern "C" void kernel_launch(void* const* d_in, const int* in_sizes, int n_in,
                              void* d_out, int out_size) {
    const float* x = (const float*)d_in[0];
    const int* edge = (const int*)d_in[1];   // int32 (JAX x64 disabled)
    const float* W1 = (const float*)d_in[2];
    const float* b1 = (const float*)d_in[3];
    const float* W2 = (const float*)d_in[4];
    const float* b2 = (const float*)d_in[5];
    const float* W3 = (const float*)d_in[6];
    const float* b3 = (const float*)d_in[7];
    const float* W4 = (const float*)d_in[8];
    const float* b4 = (const float*)d_in[9];
    const float* W5 = (const float*)d_in[10];
    const float* b5 = (const float*)d_in[11];
    const float* W6 = (const float*)d_in[12];
    const float* b6 = (const float*)d_in[13];
    const float* g1 = (const float*)d_in[14];
    const float* be1 = (const float*)d_in[15];
    const float* g2 = (const float*)d_in[16];
    const float* be2 = (const float*)d_in[17];
    const float* g3 = (const float*)d_in[18];
    const float* be3 = (const float*)d_in[19];
    const float* g4 = (const float*)d_in[20];
    const float* be4 = (const float*)d_in[21];

    int n = in_sizes[0] / 88;
    int E = in_sizes[1] / 2;
    const int* src = edge;
    const int* dst = edge + E;

    float *bufA, *bufB, *t, *dis, *stats, *sc, *sh, *csr_w;
    int *counts, *rowptr, *cursor, *csr_src;
    cudaGetSymbolAddress((void**)&bufA, g_bufA);
    cudaGetSymbolAddress((void**)&bufB, g_bufB);
    cudaGetSymbolAddress((void**)&t, g_t);
    cudaGetSymbolAddress((void**)&dis, g_dis);
    cudaGetSymbolAddress((void**)&counts, g_counts);
    cudaGetSymbolAddress((void**)&rowptr, g_rowptr);
    cudaGetSymbolAddress((void**)&cursor, g_cursor);
    cudaGetSymbolAddress((void**)&csr_src, g_csr_src);
    cudaGetSymbolAddress((void**)&csr_w, g_csr_w);
    cudaGetSymbolAddress((void**)&stats, g_stats);
    cudaGetSymbolAddress((void**)&sc, g_sc);
    cudaGetSymbolAddress((void**)&sh, g_sh);

    float* out = (float*)d_out;

    // CSR build: counts -> scan (+dis) -> scatter (+edge weights)
    zero_counts_kernel<<<(n + 255) / 256, 256>>>(counts, n);
    count_kernel<<<(E + 255) / 256, 256>>>(dst, counts, E);
    scan_kernel<<<1, 1024>>>(counts, rowptr, cursor, dis, n);
    scatter_kernel<<<(E + 255) / 256, 256>>>(src, dst, dis, cursor, csr_src, csr_w, E);

    // encoder
    run_layer<88, 70, false, true >(x,    W1, b1, t, bufA, rowptr, csr_src, csr_w, dis, n, g1, be1, stats, sc, sh);
    run_layer<70, 60, true,  true >(bufA, W2, b2, t, bufB, rowptr, csr_src, csr_w, dis, n, g2, be2, stats, sc, sh);
    run_layer<60, 50, true,  false>(bufB, W3, b3, t, bufA, rowptr, csr_src, csr_w, dis, n, nullptr, nullptr, stats, sc, sh);
    // decoder
    run_layer<50, 60, false, true >(bufA, W4, b4, t, bufB, rowptr, csr_src, csr_w, dis, n, g3, be3, stats, sc, sh);
    run_layer<60, 70, true,  true >(bufB, W5, b5, t, bufA, rowptr, csr_src, csr_w, dis, n, g4, be4, stats, sc, sh);
    run_layer<70, 88, true,  false>(bufA, W6, b6, t, out,  rowptr, csr_src, csr_w, dis, n, nullptr, nullptr, stats, sc, sh);
}

// round 5
// speedup vs baseline: 1.8417x; 1.5121x over previous
#include <cuda_runtime.h>
#include <cuda_bf16.h>

#define NMAX 50000
#define EMAX 800000

// ---- scratch (device globals; no allocation allowed) ----
__device__ __align__(16) float g_bufA[NMAX * 96];
__device__ __align__(16) float g_bufB[NMAX * 96];
__device__ __align__(16) float g_t[NMAX * 96];
__device__ float g_dis[NMAX];
__device__ int   g_counts[NMAX];
__device__ int   g_rowptr[NMAX + 1];
__device__ int   g_cursor[NMAX];
__device__ __align__(8) int2 g_meta[EMAX];   // (src, bitcast(weight))
__device__ float g_stats[256];               // [0..FO) sum, [128..128+FO) sumsq
__device__ float g_sc[128];                  // bn scale per channel
__device__ float g_sh[128];                  // bn shift per channel
__device__ __align__(16) float g_Weff[96 * 96];
__device__ __align__(16) float g_beff[96];
__device__ __align__(16) float g_tc[96];     // tconst = sh @ W (per-node additive row)

// ---------------- CSR build ----------------

__global__ void zero_counts_kernel(int* counts, int n) {
    int i = blockIdx.x * blockDim.x + threadIdx.x;
    if (i < n) counts[i] = 0;
}

__global__ void count_kernel(const int* __restrict__ dst, int* counts, int E) {
    int e = blockIdx.x * blockDim.x + threadIdx.x;
    if (e < E) atomicAdd(&counts[dst[e]], 1);
}

// single block, 1024 threads: exclusive scan of counts -> row_ptr, cursor; dis = rsqrt(deg+1)
__global__ void scan_kernel(const int* __restrict__ counts, int* __restrict__ row_ptr,
                            int* __restrict__ cursor, float* __restrict__ dis, int n) {
    __shared__ int part[1024];
    int tid = threadIdx.x;
    int chunk = (n + 1023) / 1024;
    int beg = tid * chunk;
    int end = min(beg + chunk, n);
    int s = 0;
    for (int i = beg; i < end; i++) s += counts[i];
    part[tid] = s;
    __syncthreads();
    for (int off = 1; off < 1024; off <<= 1) {
        int v = part[tid];
        int add = (tid >= off) ? part[tid - off] : 0;
        __syncthreads();
        part[tid] = v + add;
        __syncthreads();
    }
    int run = (tid > 0) ? part[tid - 1] : 0;
    for (int i = beg; i < end; i++) {
        int c = counts[i];
        row_ptr[i] = run;
        cursor[i] = run;
        dis[i] = rsqrtf((float)c + 1.0f);
        run += c;
    }
    if (tid == 1023) row_ptr[n] = part[1023];
}

__global__ void scatter_kernel(const int* __restrict__ src, const int* __restrict__ dst,
                               const float* __restrict__ dis,
                               int* __restrict__ cursor, int2* __restrict__ meta, int E) {
    int e = blockIdx.x * blockDim.x + threadIdx.x;
    if (e >= E) return;
    int s = src[e];
    int d = dst[e];
    int pos = atomicAdd(&cursor[d], 1);
    meta[pos] = make_int2(s, __float_as_int(dis[s] * dis[d]));
}

// ---------------- per-layer prep: fold BN scale into W, tconst = sh@W, pad, zero stats ----------------

template <int FI, int FIS, int FO, int FOS, bool AFF>
__global__ void prep_kernel(const float* __restrict__ W, const float* __restrict__ b,
                            const float* __restrict__ sc, const float* __restrict__ sh,
                            float* __restrict__ Weff, float* __restrict__ beff,
                            float* __restrict__ tc, float* __restrict__ stats) {
    int tid = threadIdx.x;  // 256 threads, 1 block
    stats[tid] = 0.0f;
    for (int idx = tid; idx < FIS * FOS; idx += 256) {
        int k = idx / FOS;
        int c = idx - k * FOS;
        float v = 0.0f;
        if (k < FI && c < FO) {
            v = W[k * FO + c];
            if (AFF) v *= sc[k];
        }
        Weff[idx] = v;
    }
    if (tid < FOS) {
        float bv = 0.0f, tv = 0.0f;
        if (tid < FO) {
            bv = b[tid];
            if (AFF) {
                float s = 0.0f;
                for (int k = 0; k < FI; k++) s += sh[k] * W[k * FO + tid];
                tv = s;
            }
        }
        beff[tid] = bv;
        tc[tid] = tv;
    }
}

// ---------------- GEMM: one thread per row, acc pairs in regs, fma.rn.f32x2 ----------------

template <int FIS, int FOS>
__global__ void __launch_bounds__(128) gemm_kernel(const float* __restrict__ x,
                                                   const float* __restrict__ Weff,
                                                   const float* __restrict__ tc,
                                                   float* __restrict__ t, int n) {
    __shared__ __align__(16) float sW[FIS * FOS];
    for (int i = threadIdx.x * 4; i < FIS * FOS; i += 128 * 4)
        *(float4*)&sW[i] = *(const float4*)&Weff[i];
    __syncthreads();
    int row = blockIdx.x * 128 + threadIdx.x;
    if (row >= n) return;
    const float4* xr = (const float4*)(x + (size_t)row * FIS);
    constexpr int NP = FOS / 2;
    unsigned long long acc[NP];
    const unsigned long long* tcp = (const unsigned long long*)tc;
#pragma unroll
    for (int p = 0; p < NP; p++) acc[p] = __ldg(&tcp[p]);   // init with tconst = sh@W
#pragma unroll 1
    for (int k4 = 0; k4 < FIS / 4; k4++) {
        float4 xv = __ldg(&xr[k4]);
#pragma unroll
        for (int j = 0; j < 4; j++) {
            float xk = (j == 0) ? xv.x : (j == 1) ? xv.y : (j == 2) ? xv.z : xv.w;
            unsigned long long a2;
            asm("mov.b64 %0, {%1, %1};" : "=l"(a2) : "r"(__float_as_uint(xk)));
            const unsigned long long* wrow =
                (const unsigned long long*)&sW[(k4 * 4 + j) * FOS];
#pragma unroll
            for (int p = 0; p < NP; p++) {
                unsigned long long b2 = wrow[p];
                asm("fma.rn.f32x2 %0, %1, %2, %0;" : "+l"(acc[p]) : "l"(a2), "l"(b2));
            }
        }
    }
    float* tr = t + (size_t)row * FOS;
#pragma unroll
    for (int p = 0; p < NP; p += 2) {
        ulonglong2 v;
        v.x = acc[p];
        v.y = acc[p + 1];
        *(ulonglong2*)&tr[p * 2] = v;
    }
}

// ---------------- CSR aggregation: warp per node, float4 gathers, fused bias/relu/stats ----------------

template <int FO, int FOS, bool RS>
__global__ void agg_kernel(const int* __restrict__ rp, const int2* __restrict__ meta,
                           const float* __restrict__ t, const float* __restrict__ dis,
                           const float* __restrict__ beff, float* __restrict__ out,
                           float* __restrict__ stats, int n) {
    __shared__ float ssum[RS ? FO : 1];
    __shared__ float ssq[RS ? FO : 1];
    if (RS) {
        for (int i = threadIdx.x; i < FO; i += blockDim.x) { ssum[i] = 0.0f; ssq[i] = 0.0f; }
        __syncthreads();
    }
    int lane = threadIdx.x & 31;
    int warp = (blockIdx.x * blockDim.x + threadIdx.x) >> 5;
    int nwarps = (gridDim.x * blockDim.x) >> 5;
    int cb = lane * 4;
    bool act = cb < FOS;
    float4 bias = make_float4(0.f, 0.f, 0.f, 0.f);
    if (act) bias = *(const float4*)&beff[cb];
    float4 psum = make_float4(0.f, 0.f, 0.f, 0.f);
    float4 psq = make_float4(0.f, 0.f, 0.f, 0.f);

    for (int i = warp; i < n; i += nwarps) {
        float dd = dis[i];
        float d2 = dd * dd;
        float4 acc = bias;
        if (act) {
            float4 tv = *(const float4*)&t[(size_t)i * FOS + cb];
            acc.x += tv.x * d2; acc.y += tv.y * d2; acc.z += tv.z * d2; acc.w += tv.w * d2;
        }
        int beg = __ldg(&rp[i]);
        int end = __ldg(&rp[i + 1]);
        int j = beg;
        for (; j + 3 < end; j += 4) {
            int2 m0 = __ldg(&meta[j]);
            int2 m1 = __ldg(&meta[j + 1]);
            int2 m2 = __ldg(&meta[j + 2]);
            int2 m3 = __ldg(&meta[j + 3]);
            if (act) {
                float4 v0 = *(const float4*)&t[(size_t)m0.x * FOS + cb];
                float4 v1 = *(const float4*)&t[(size_t)m1.x * FOS + cb];
                float4 v2 = *(const float4*)&t[(size_t)m2.x * FOS + cb];
                float4 v3 = *(const float4*)&t[(size_t)m3.x * FOS + cb];
                float w0 = __int_as_float(m0.y), w1 = __int_as_float(m1.y);
                float w2 = __int_as_float(m2.y), w3 = __int_as_float(m3.y);
                acc.x += v0.x * w0; acc.y += v0.y * w0; acc.z += v0.z * w0; acc.w += v0.w * w0;
                acc.x += v1.x * w1; acc.y += v1.y * w1; acc.z += v1.z * w1; acc.w += v1.w * w1;
                acc.x += v2.x * w2; acc.y += v2.y * w2; acc.z += v2.z * w2; acc.w += v2.w * w2;
                acc.x += v3.x * w3; acc.y += v3.y * w3; acc.z += v3.z * w3; acc.w += v3.w * w3;
            }
        }
        for (; j < end; j++) {
            int2 m0 = __ldg(&meta[j]);
            if (act) {
                float4 v0 = *(const float4*)&t[(size_t)m0.x * FOS + cb];
                float w0 = __int_as_float(m0.y);
                acc.x += v0.x * w0; acc.y += v0.y * w0; acc.z += v0.z * w0; acc.w += v0.w * w0;
            }
        }
        if (act) {
            if (FOS > FO) {  // zero pad channels so next layer can include them blindly
                if (cb + 0 >= FO) acc.x = 0.0f;
                if (cb + 1 >= FO) acc.y = 0.0f;
                if (cb + 2 >= FO) acc.z = 0.0f;
                if (cb + 3 >= FO) acc.w = 0.0f;
            }
            if (RS) {
                acc.x = fmaxf(acc.x, 0.f); acc.y = fmaxf(acc.y, 0.f);
                acc.z = fmaxf(acc.z, 0.f); acc.w = fmaxf(acc.w, 0.f);
                psum.x += acc.x; psq.x += acc.x * acc.x;
                psum.y += acc.y; psq.y += acc.y * acc.y;
                psum.z += acc.z; psq.z += acc.z * acc.z;
                psum.w += acc.w; psq.w += acc.w * acc.w;
            }
            *(float4*)&out[(size_t)i * FOS + cb] = acc;
        }
    }

    if (RS) {
        if (act) {
            if (cb + 0 < FO) { atomicAdd(&ssum[cb + 0], psum.x); atomicAdd(&ssq[cb + 0], psq.x); }
            if (cb + 1 < FO) { atomicAdd(&ssum[cb + 1], psum.y); atomicAdd(&ssq[cb + 1], psq.y); }
            if (cb + 2 < FO) { atomicAdd(&ssum[cb + 2], psum.z); atomicAdd(&ssq[cb + 2], psq.z); }
            if (cb + 3 < FO) { atomicAdd(&ssum[cb + 3], psum.w); atomicAdd(&ssq[cb + 3], psq.w); }
        }
        __syncthreads();
        for (int i = threadIdx.x; i < FO; i += blockDim.x) {
            atomicAdd(&stats[i], ssum[i]);
            atomicAdd(&stats[128 + i], ssq[i]);
        }
    }
}

// ---------------- BN finalize: sc/sh per channel ----------------

template <int FO>
__global__ void bn_finalize_kernel(const float* __restrict__ stats,
                                   const float* __restrict__ g, const float* __restrict__ be,
                                   float* __restrict__ sc, float* __restrict__ sh, int n) {
    int c = threadIdx.x;
    if (c >= FO) return;
    float inv_n = 1.0f / (float)n;
    float mu = stats[c] * inv_n;
    float var = stats[128 + c] * inv_n - mu * mu;
    float s = g[c] * rsqrtf(var + 1e-5f);
    sc[c] = s;
    sh[c] = be[c] - mu * s;
}

// ---------------- host driver ----------------

struct Ctx {
    float *bufA, *bufB, *t, *dis, *stats, *sc, *sh, *Weff, *beff, *tc;
    int *rp;
    int2* meta;
    int n;
};

template <int FI, int FIS, int FO, int FOS, bool AFF, bool BN>
static void run_layer(const Ctx& c, const float* in, const float* W, const float* b,
                      float* out, const float* g, const float* be) {
    prep_kernel<FI, FIS, FO, FOS, AFF><<<1, 256>>>(W, b, c.sc, c.sh, c.Weff, c.beff, c.tc, c.stats);
    gemm_kernel<FIS, FOS><<<(c.n + 127) / 128, 128>>>(in, c.Weff, c.tc, c.t, c.n);
    agg_kernel<FO, FOS, BN><<<1024, 256>>>(c.rp, c.meta, c.t, c.dis, c.beff, out, c.stats, c.n);
    if (BN) bn_finalize_kernel<FO><<<1, 128>>>(c.stats, g, be, c.sc, c.sh, c.n);
}

extern "C" void kernel_launch(void* const* d_in, const int* in_sizes, int n_in,
                              void* d_out, int out_size) {
    const float* x = (const float*)d_in[0];
    const int* edge = (const int*)d_in[1];   // int32 (JAX x64 disabled)
    const float* W1 = (const float*)d_in[2];
    const float* b1 = (const float*)d_in[3];
    const float* W2 = (const float*)d_in[4];
    const float* b2 = (const float*)d_in[5];
    const float* W3 = (const float*)d_in[6];
    const float* b3 = (const float*)d_in[7];
    const float* W4 = (const float*)d_in[8];
    const float* b4 = (const float*)d_in[9];
    const float* W5 = (const float*)d_in[10];
    const float* b5 = (const float*)d_in[11];
    const float* W6 = (const float*)d_in[12];
    const float* b6 = (const float*)d_in[13];
    const float* g1 = (const float*)d_in[14];
    const float* be1 = (const float*)d_in[15];
    const float* g2 = (const float*)d_in[16];
    const float* be2 = (const float*)d_in[17];
    const float* g3 = (const float*)d_in[18];
    const float* be3 = (const float*)d_in[19];
    const float* g4 = (const float*)d_in[20];
    const float* be4 = (const float*)d_in[21];

    int n = in_sizes[0] / 88;
    int E = in_sizes[1] / 2;
    const int* src = edge;
    const int* dst = edge + E;

    Ctx c;
    int *counts, *cursor;
    cudaGetSymbolAddress((void**)&c.bufA, g_bufA);
    cudaGetSymbolAddress((void**)&c.bufB, g_bufB);
    cudaGetSymbolAddress((void**)&c.t, g_t);
    cudaGetSymbolAddress((void**)&c.dis, g_dis);
    cudaGetSymbolAddress((void**)&counts, g_counts);
    cudaGetSymbolAddress((void**)&c.rp, g_rowptr);
    cudaGetSymbolAddress((void**)&cursor, g_cursor);
    cudaGetSymbolAddress((void**)&c.meta, g_meta);
    cudaGetSymbolAddress((void**)&c.stats, g_stats);
    cudaGetSymbolAddress((void**)&c.sc, g_sc);
    cudaGetSymbolAddress((void**)&c.sh, g_sh);
    cudaGetSymbolAddress((void**)&c.Weff, g_Weff);
    cudaGetSymbolAddress((void**)&c.beff, g_beff);
    cudaGetSymbolAddress((void**)&c.tc, g_tc);
    c.n = n;

    float* out = (float*)d_out;

    // CSR build
    zero_counts_kernel<<<(n + 255) / 256, 256>>>(counts, n);
    count_kernel<<<(E + 255) / 256, 256>>>(dst, counts, E);
    scan_kernel<<<1, 1024>>>(counts, c.rp, cursor, c.dis, n);
    scatter_kernel<<<(E + 255) / 256, 256>>>(src, dst, c.dis, cursor, c.meta, E);

    // encoder
    run_layer<88, 88, 70, 72, false, true >(c, x,      W1, b1, c.bufA, g1, be1);
    run_layer<70, 72, 60, 60, true,  true >(c, c.bufA, W2, b2, c.bufB, g2, be2);
    run_layer<60, 60, 50, 52, true,  false>(c, c.bufB, W3, b3, c.bufA, nullptr, nullptr);
    // decoder
    run_layer<50, 52, 60, 60, false, true >(c, c.bufA, W4, b4, c.bufB, g3, be3);
    run_layer<60, 60, 70, 72, true,  true >(c, c.bufB, W5, b5, c.bufA, g4, be4);
    run_layer<70, 72, 88, 88, true,  false>(c, c.bufA, W6, b6, out, nullptr, nullptr);
}

// round 6
// speedup vs baseline: 1.9241x; 1.0448x over previous
#include <cuda_runtime.h>
#include <cuda_bf16.h>

#define NMAX 50000
#define EMAX 800000

// ---- scratch (device globals; no allocation allowed) ----
__device__ __align__(16) float g_bufA[NMAX * 96];
__device__ __align__(16) float g_bufB[NMAX * 96];
__device__ __align__(16) float g_t[NMAX * 96];
__device__ float g_dis[NMAX];
__device__ int   g_counts[NMAX];
__device__ int   g_rowptr[NMAX + 1];
__device__ int   g_cursor[NMAX];
__device__ __align__(16) int2 g_meta[EMAX];  // (src, bitcast(weight)), 16B-aligned for int4 loads
__device__ float g_statsA[256];              // [0..128) sum, [128..256) sumsq
__device__ float g_statsB[256];

// ---------------- CSR build ----------------

__global__ void zero_counts_kernel(int* counts, int n) {
    int i = blockIdx.x * blockDim.x + threadIdx.x;
    if (i < n) counts[i] = 0;
}

__global__ void count_kernel(const int* __restrict__ dst, int* counts, int E) {
    int e = blockIdx.x * blockDim.x + threadIdx.x;
    if (e < E) atomicAdd(&counts[dst[e]], 1);
}

// single block, 1024 threads: exclusive scan of counts -> row_ptr, cursor; dis = rsqrt(deg+1)
__global__ void scan_kernel(const int* __restrict__ counts, int* __restrict__ row_ptr,
                            int* __restrict__ cursor, float* __restrict__ dis, int n) {
    __shared__ int part[1024];
    int tid = threadIdx.x;
    int chunk = (n + 1023) / 1024;
    int beg = tid * chunk;
    int end = min(beg + chunk, n);
    int s = 0;
    for (int i = beg; i < end; i++) s += counts[i];
    part[tid] = s;
    __syncthreads();
    for (int off = 1; off < 1024; off <<= 1) {
        int v = part[tid];
        int add = (tid >= off) ? part[tid - off] : 0;
        __syncthreads();
        part[tid] = v + add;
        __syncthreads();
    }
    int run = (tid > 0) ? part[tid - 1] : 0;
    for (int i = beg; i < end; i++) {
        int c = counts[i];
        row_ptr[i] = run;
        cursor[i] = run;
        dis[i] = rsqrtf((float)c + 1.0f);
        run += c;
    }
    if (tid == 1023) row_ptr[n] = part[1023];
}

__global__ void scatter_kernel(const int* __restrict__ src, const int* __restrict__ dst,
                               const float* __restrict__ dis,
                               int* __restrict__ cursor, int2* __restrict__ meta, int E) {
    int e = blockIdx.x * blockDim.x + threadIdx.x;
    if (e >= E) return;
    int s = src[e];
    int d = dst[e];
    int pos = atomicAdd(&cursor[d], 1);
    meta[pos] = make_int2(s, __float_as_int(dis[s] * dis[d]));
}

// ---------------- fused GEMM: bn-finalize + affine-fold + gemm (fma.rn.f32x2, LDS.128) ------------
// t[row] = (AFF ? (in*sc+sh) : in) @ W   computed as  in @ (sc.*W) + (sh@W)
// sc/sh derived in-block from stats_prev + g/be. Block 0 optionally zeroes stats_cur.

template <int FI, int FIS, int FO, int FOS, bool AFF, bool ZERO>
__global__ void __launch_bounds__(128) gemm_kernel(
        const float* __restrict__ x, const float* __restrict__ W,
        const float* __restrict__ g, const float* __restrict__ be,
        const float* __restrict__ stats_prev, float* __restrict__ stats_cur,
        float* __restrict__ t, int n) {
    __shared__ __align__(16) float sW[FIS * FOS];
    __shared__ __align__(16) float s_tc[FOS];
    __shared__ float s_sc[96], s_sh[96];
    int tid = threadIdx.x;

    if (AFF) {
        if (tid < FI) {
            float inv_n = 1.0f / (float)n;
            float mu = stats_prev[tid] * inv_n;
            float var = stats_prev[128 + tid] * inv_n - mu * mu;
            float s = g[tid] * rsqrtf(var + 1e-5f);
            s_sc[tid] = s;
            s_sh[tid] = be[tid] - mu * s;
        }
        __syncthreads();
    }
    if (ZERO && blockIdx.x == 0) {
        stats_cur[tid] = 0.0f;
        stats_cur[tid + 128] = 0.0f;
    }
    // stage W (BN-scaled, zero-padded) to smem
    for (int idx = tid; idx < FIS * FOS; idx += 128) {
        int k = idx / FOS;
        int c = idx - k * FOS;
        float v = 0.0f;
        if (k < FI && c < FO) {
            v = __ldg(&W[k * FO + c]);
            if (AFF) v *= s_sc[k];
        }
        sW[idx] = v;
    }
    // tconst = sh @ W (original W)
    if (tid < FOS) {
        float tv = 0.0f;
        if (AFF && tid < FO) {
#pragma unroll 8
            for (int k = 0; k < FI; k++) tv += s_sh[k] * __ldg(&W[k * FO + tid]);
        }
        s_tc[tid] = tv;
    }
    __syncthreads();

    int row = blockIdx.x * 128 + tid;
    if (row >= n) return;
    const float4* xr = (const float4*)(x + (size_t)row * FIS);
    constexpr int NP = FOS / 2;  // even (FOS % 4 == 0)
    unsigned long long acc[NP];
    const unsigned long long* tcp = (const unsigned long long*)s_tc;
#pragma unroll
    for (int p = 0; p < NP; p++) acc[p] = tcp[p];
#pragma unroll 1
    for (int k4 = 0; k4 < FIS / 4; k4++) {
        float4 xv = __ldg(&xr[k4]);
#pragma unroll
        for (int j = 0; j < 4; j++) {
            float xk = (j == 0) ? xv.x : (j == 1) ? xv.y : (j == 2) ? xv.z : xv.w;
            unsigned long long a2;
            asm("mov.b64 %0, {%1, %1};" : "=l"(a2) : "r"(__float_as_uint(xk)));
            const float* wr = &sW[(k4 * 4 + j) * FOS];
#pragma unroll
            for (int p = 0; p < NP; p += 2) {
                ulonglong2 w2 = *(const ulonglong2*)(wr + 2 * p);
                asm("fma.rn.f32x2 %0, %1, %2, %0;" : "+l"(acc[p]) : "l"(a2), "l"(w2.x));
                asm("fma.rn.f32x2 %0, %1, %2, %0;" : "+l"(acc[p + 1]) : "l"(a2), "l"(w2.y));
            }
        }
    }
    float* tr = t + (size_t)row * FOS;
#pragma unroll
    for (int p = 0; p < NP; p += 2) {
        ulonglong2 v;
        v.x = acc[p];
        v.y = acc[p + 1];
        *(ulonglong2*)&tr[p * 2] = v;
    }
}

// ---------------- CSR aggregation: warp per node, float4 gathers, paired meta, fused relu/stats ----

template <int FO, int FOS, bool RS>
__global__ void agg_kernel(const int* __restrict__ rp, const int2* __restrict__ meta,
                           const float* __restrict__ t, const float* __restrict__ dis,
                           const float* __restrict__ b, float* __restrict__ out,
                           float* __restrict__ stats, int n) {
    __shared__ float ssum[RS ? FO : 1];
    __shared__ float ssq[RS ? FO : 1];
    if (RS) {
        for (int i = threadIdx.x; i < FO; i += blockDim.x) { ssum[i] = 0.0f; ssq[i] = 0.0f; }
        __syncthreads();
    }
    int lane = threadIdx.x & 31;
    int warp = (blockIdx.x * blockDim.x + threadIdx.x) >> 5;
    int nwarps = (gridDim.x * blockDim.x) >> 5;
    int cb = lane * 4;
    bool act = cb < FOS;
    float4 bias = make_float4(0.f, 0.f, 0.f, 0.f);
    if (cb + 0 < FO) bias.x = __ldg(&b[cb + 0]);
    if (cb + 1 < FO) bias.y = __ldg(&b[cb + 1]);
    if (cb + 2 < FO) bias.z = __ldg(&b[cb + 2]);
    if (cb + 3 < FO) bias.w = __ldg(&b[cb + 3]);
    float4 psum = make_float4(0.f, 0.f, 0.f, 0.f);
    float4 psq = make_float4(0.f, 0.f, 0.f, 0.f);

    for (int i = warp; i < n; i += nwarps) {
        float dd = dis[i];
        float d2 = dd * dd;
        float4 acc = bias;
        if (act) {
            float4 tv = __ldg((const float4*)&t[(size_t)i * FOS + cb]);
            acc.x += tv.x * d2; acc.y += tv.y * d2; acc.z += tv.z * d2; acc.w += tv.w * d2;
        }
        int beg = __ldg(&rp[i]);
        int end = __ldg(&rp[i + 1]);
        int j = beg;
        if (j < end && (j & 1)) {  // align to even index for int4 meta loads
            int2 m = __ldg(&meta[j]);
            if (act) {
                float4 v = __ldg((const float4*)&t[(size_t)m.x * FOS + cb]);
                float w = __int_as_float(m.y);
                acc.x += v.x * w; acc.y += v.y * w; acc.z += v.z * w; acc.w += v.w * w;
            }
            j++;
        }
        for (; j + 3 < end; j += 4) {
            int4 ma = __ldg((const int4*)&meta[j]);      // edges j, j+1
            int4 mb = __ldg((const int4*)&meta[j + 2]);  // edges j+2, j+3
            if (act) {
                float4 v0 = __ldg((const float4*)&t[(size_t)ma.x * FOS + cb]);
                float4 v1 = __ldg((const float4*)&t[(size_t)ma.z * FOS + cb]);
                float4 v2 = __ldg((const float4*)&t[(size_t)mb.x * FOS + cb]);
                float4 v3 = __ldg((const float4*)&t[(size_t)mb.z * FOS + cb]);
                float w0 = __int_as_float(ma.y), w1 = __int_as_float(ma.w);
                float w2 = __int_as_float(mb.y), w3 = __int_as_float(mb.w);
                acc.x += v0.x * w0; acc.y += v0.y * w0; acc.z += v0.z * w0; acc.w += v0.w * w0;
                acc.x += v1.x * w1; acc.y += v1.y * w1; acc.z += v1.z * w1; acc.w += v1.w * w1;
                acc.x += v2.x * w2; acc.y += v2.y * w2; acc.z += v2.z * w2; acc.w += v2.w * w2;
                acc.x += v3.x * w3; acc.y += v3.y * w3; acc.z += v3.z * w3; acc.w += v3.w * w3;
            }
        }
        if (j + 1 < end) {
            int4 ma = __ldg((const int4*)&meta[j]);
            if (act) {
                float4 v0 = __ldg((const float4*)&t[(size_t)ma.x * FOS + cb]);
                float4 v1 = __ldg((const float4*)&t[(size_t)ma.z * FOS + cb]);
                float w0 = __int_as_float(ma.y), w1 = __int_as_float(ma.w);
                acc.x += v0.x * w0; acc.y += v0.y * w0; acc.z += v0.z * w0; acc.w += v0.w * w0;
                acc.x += v1.x * w1; acc.y += v1.y * w1; acc.z += v1.z * w1; acc.w += v1.w * w1;
            }
            j += 2;
        }
        if (j < end) {
            int2 m = __ldg(&meta[j]);
            if (act) {
                float4 v = __ldg((const float4*)&t[(size_t)m.x * FOS + cb]);
                float w = __int_as_float(m.y);
                acc.x += v.x * w; acc.y += v.y * w; acc.z += v.z * w; acc.w += v.w * w;
            }
        }
        if (act) {
            if (RS) {
                acc.x = fmaxf(acc.x, 0.f); acc.y = fmaxf(acc.y, 0.f);
                acc.z = fmaxf(acc.z, 0.f); acc.w = fmaxf(acc.w, 0.f);
                psum.x += acc.x; psq.x += acc.x * acc.x;
                psum.y += acc.y; psq.y += acc.y * acc.y;
                psum.z += acc.z; psq.z += acc.z * acc.z;
                psum.w += acc.w; psq.w += acc.w * acc.w;
            }
            *(float4*)&out[(size_t)i * FOS + cb] = acc;
        }
    }

    if (RS) {
        if (act) {
            if (cb + 0 < FO) { atomicAdd(&ssum[cb + 0], psum.x); atomicAdd(&ssq[cb + 0], psq.x); }
            if (cb + 1 < FO) { atomicAdd(&ssum[cb + 1], psum.y); atomicAdd(&ssq[cb + 1], psq.y); }
            if (cb + 2 < FO) { atomicAdd(&ssum[cb + 2], psum.z); atomicAdd(&ssq[cb + 2], psq.z); }
            if (cb + 3 < FO) { atomicAdd(&ssum[cb + 3], psum.w); atomicAdd(&ssq[cb + 3], psq.w); }
        }
        __syncthreads();
        for (int i = threadIdx.x; i < FO; i += blockDim.x) {
            atomicAdd(&stats[i], ssum[i]);
            atomicAdd(&stats[128 + i], ssq[i]);
        }
    }
}

// ---------------- host driver ----------------

extern "C" void kernel_launch(void* const* d_in, const int* in_sizes, int n_in,
                              void* d_out, int out_size) {
    const float* x = (const float*)d_in[0];
    const int* edge = (const int*)d_in[1];   // int32 (JAX x64 disabled)
    const float* W1 = (const float*)d_in[2];
    const float* b1 = (const float*)d_in[3];
    const float* W2 = (const float*)d_in[4];
    const float* b2 = (const float*)d_in[5];
    const float* W3 = (const float*)d_in[6];
    const float* b3 = (const float*)d_in[7];
    const float* W4 = (const float*)d_in[8];
    const float* b4 = (const float*)d_in[9];
    const float* W5 = (const float*)d_in[10];
    const float* b5 = (const float*)d_in[11];
    const float* W6 = (const float*)d_in[12];
    const float* b6 = (const float*)d_in[13];
    const float* g1 = (const float*)d_in[14];
    const float* be1 = (const float*)d_in[15];
    const float* g2 = (const float*)d_in[16];
    const float* be2 = (const float*)d_in[17];
    const float* g3 = (const float*)d_in[18];
    const float* be3 = (const float*)d_in[19];
    const float* g4 = (const float*)d_in[20];
    const float* be4 = (const float*)d_in[21];

    int n = in_sizes[0] / 88;
    int E = in_sizes[1] / 2;
    const int* src = edge;
    const int* dst = edge + E;

    float *bufA, *bufB, *t, *dis, *sA, *sB;
    int *counts, *rp, *cursor;
    int2* meta;
    cudaGetSymbolAddress((void**)&bufA, g_bufA);
    cudaGetSymbolAddress((void**)&bufB, g_bufB);
    cudaGetSymbolAddress((void**)&t, g_t);
    cudaGetSymbolAddress((void**)&dis, g_dis);
    cudaGetSymbolAddress((void**)&counts, g_counts);
    cudaGetSymbolAddress((void**)&rp, g_rowptr);
    cudaGetSymbolAddress((void**)&cursor, g_cursor);
    cudaGetSymbolAddress((void**)&meta, g_meta);
    cudaGetSymbolAddress((void**)&sA, g_statsA);
    cudaGetSymbolAddress((void**)&sB, g_statsB);

    float* out = (float*)d_out;
    int gb = (n + 127) / 128;

    // CSR build
    zero_counts_kernel<<<(n + 255) / 256, 256>>>(counts, n);
    count_kernel<<<(E + 255) / 256, 256>>>(dst, counts, E);
    scan_kernel<<<1, 1024>>>(counts, rp, cursor, dis, n);
    scatter_kernel<<<(E + 255) / 256, 256>>>(src, dst, dis, cursor, meta, E);

    // L1: 88->70 (relu+bn -> statsA)
    gemm_kernel<88, 88, 70, 72, false, true><<<gb, 128>>>(x, W1, nullptr, nullptr, nullptr, sA, t, n);
    agg_kernel<70, 72, true><<<1024, 256>>>(rp, meta, t, dis, b1, bufA, sA, n);
    // L2: 70->60 (affine from statsA/g1, relu+bn -> statsB)
    gemm_kernel<70, 72, 60, 60, true, true><<<gb, 128>>>(bufA, W2, g1, be1, sA, sB, t, n);
    agg_kernel<60, 60, true><<<1024, 256>>>(rp, meta, t, dis, b2, bufB, sB, n);
    // L3: 60->50 (affine from statsB/g2, no bn)
    gemm_kernel<60, 60, 50, 52, true, false><<<gb, 128>>>(bufB, W3, g2, be2, sB, nullptr, t, n);
    agg_kernel<50, 52, false><<<1024, 256>>>(rp, meta, t, dis, b3, bufA, nullptr, n);
    // L4: 50->60 (no affine, relu+bn -> statsA)
    gemm_kernel<50, 52, 60, 60, false, true><<<gb, 128>>>(bufA, W4, nullptr, nullptr, nullptr, sA, t, n);
    agg_kernel<60, 60, true><<<1024, 256>>>(rp, meta, t, dis, b4, bufB, sA, n);
    // L5: 60->70 (affine from statsA/g3, relu+bn -> statsB)
    gemm_kernel<60, 60, 70, 72, true, true><<<gb, 128>>>(bufB, W5, g3, be3, sA, sB, t, n);
    agg_kernel<70, 72, true><<<1024, 256>>>(rp, meta, t, dis, b5, bufA, sB, n);
    // L6: 70->88 (affine from statsB/g4, no bn) -> out
    gemm_kernel<70, 72, 88, 88, true, false><<<gb, 128>>>(bufA, W6, g4, be4, sB, nullptr, t, n);
    agg_kernel<88, 88, false><<<1024, 256>>>(rp, meta, t, dis, b6, out, nullptr, n);
}

// round 7
// speedup vs baseline: 1.9587x; 1.0180x over previous
#include <cuda_runtime.h>
#include <cuda_bf16.h>

#define NMAX 50000
#define EMAX 800000

// ---- scratch (device globals; no allocation allowed) ----
__device__ __align__(16) float g_bufA[NMAX * 96];
__device__ __align__(16) float g_bufB[NMAX * 96];
__device__ __align__(16) float g_t[NMAX * 96];
__device__ float g_dis[NMAX];
__device__ int   g_counts[NMAX];
__device__ int   g_rowptr[NMAX + 1];
__device__ int   g_cursor[NMAX];
__device__ __align__(16) int2 g_meta[EMAX];  // (src, bitcast(weight)), 16B-aligned for int4 loads
__device__ float g_statsA[256];              // [0..128) sum, [128..256) sumsq
__device__ float g_statsB[256];

// ---------------- CSR build ----------------

__global__ void zero_counts_kernel(int* counts, int n) {
    int i = blockIdx.x * blockDim.x + threadIdx.x;
    if (i < n) counts[i] = 0;
}

__global__ void count_kernel(const int* __restrict__ dst, int* counts, int E) {
    int e = blockIdx.x * blockDim.x + threadIdx.x;
    if (e < E) atomicAdd(&counts[dst[e]], 1);
}

// single block, 1024 threads: exclusive scan of counts -> row_ptr, cursor; dis = rsqrt(deg+1)
__global__ void scan_kernel(const int* __restrict__ counts, int* __restrict__ row_ptr,
                            int* __restrict__ cursor, float* __restrict__ dis, int n) {
    __shared__ int part[1024];
    int tid = threadIdx.x;
    int chunk = (n + 1023) / 1024;
    int beg = tid * chunk;
    int end = min(beg + chunk, n);
    int s = 0;
    for (int i = beg; i < end; i++) s += counts[i];
    part[tid] = s;
    __syncthreads();
    for (int off = 1; off < 1024; off <<= 1) {
        int v = part[tid];
        int add = (tid >= off) ? part[tid - off] : 0;
        __syncthreads();
        part[tid] = v + add;
        __syncthreads();
    }
    int run = (tid > 0) ? part[tid - 1] : 0;
    for (int i = beg; i < end; i++) {
        int c = counts[i];
        row_ptr[i] = run;
        cursor[i] = run;
        dis[i] = rsqrtf((float)c + 1.0f);
        run += c;
    }
    if (tid == 1023) row_ptr[n] = part[1023];
}

__global__ void scatter_kernel(const int* __restrict__ src, const int* __restrict__ dst,
                               const float* __restrict__ dis,
                               int* __restrict__ cursor, int2* __restrict__ meta, int E) {
    int e = blockIdx.x * blockDim.x + threadIdx.x;
    if (e >= E) return;
    int s = src[e];
    int d = dst[e];
    int pos = atomicAdd(&cursor[d], 1);
    meta[pos] = make_int2(s, __float_as_int(dis[s] * dis[d]));
}

// ---------------- fused GEMM: bn-finalize + affine-fold + gemm (fma.rn.f32x2, LDS.128) ------------

template <int FI, int FIS, int FO, int FOS, bool AFF, bool ZERO>
__global__ void __launch_bounds__(128) gemm_kernel(
        const float* __restrict__ x, const float* __restrict__ W,
        const float* __restrict__ g, const float* __restrict__ be,
        const float* __restrict__ stats_prev, float* __restrict__ stats_cur,
        float* __restrict__ t, int n) {
    __shared__ __align__(16) float sW[FIS * FOS];
    __shared__ __align__(16) float s_tc[FOS];
    __shared__ float s_sc[96], s_sh[96];
    int tid = threadIdx.x;

    if (AFF) {
        if (tid < FI) {
            float inv_n = 1.0f / (float)n;
            float mu = stats_prev[tid] * inv_n;
            float var = stats_prev[128 + tid] * inv_n - mu * mu;
            float s = g[tid] * rsqrtf(var + 1e-5f);
            s_sc[tid] = s;
            s_sh[tid] = be[tid] - mu * s;
        }
        __syncthreads();
    }
    if (ZERO && blockIdx.x == 0) {
        stats_cur[tid] = 0.0f;
        stats_cur[tid + 128] = 0.0f;
    }
    for (int idx = tid; idx < FIS * FOS; idx += 128) {
        int k = idx / FOS;
        int c = idx - k * FOS;
        float v = 0.0f;
        if (k < FI && c < FO) {
            v = __ldg(&W[k * FO + c]);
            if (AFF) v *= s_sc[k];
        }
        sW[idx] = v;
    }
    if (tid < FOS) {
        float tv = 0.0f;
        if (AFF && tid < FO) {
#pragma unroll 8
            for (int k = 0; k < FI; k++) tv += s_sh[k] * __ldg(&W[k * FO + tid]);
        }
        s_tc[tid] = tv;
    }
    __syncthreads();

    int row = blockIdx.x * 128 + tid;
    if (row >= n) return;
    const float4* xr = (const float4*)(x + (size_t)row * FIS);
    constexpr int NP = FOS / 2;  // even (FOS % 4 == 0)
    unsigned long long acc[NP];
    const unsigned long long* tcp = (const unsigned long long*)s_tc;
#pragma unroll
    for (int p = 0; p < NP; p++) acc[p] = tcp[p];
#pragma unroll 1
    for (int k4 = 0; k4 < FIS / 4; k4++) {
        float4 xv = __ldg(&xr[k4]);
#pragma unroll
        for (int j = 0; j < 4; j++) {
            float xk = (j == 0) ? xv.x : (j == 1) ? xv.y : (j == 2) ? xv.z : xv.w;
            unsigned long long a2;
            asm("mov.b64 %0, {%1, %1};" : "=l"(a2) : "r"(__float_as_uint(xk)));
            const float* wr = &sW[(k4 * 4 + j) * FOS];
#pragma unroll
            for (int p = 0; p < NP; p += 2) {
                ulonglong2 w2 = *(const ulonglong2*)(wr + 2 * p);
                asm("fma.rn.f32x2 %0, %1, %2, %0;" : "+l"(acc[p]) : "l"(a2), "l"(w2.x));
                asm("fma.rn.f32x2 %0, %1, %2, %0;" : "+l"(acc[p + 1]) : "l"(a2), "l"(w2.y));
            }
        }
    }
    float* tr = t + (size_t)row * FOS;
#pragma unroll
    for (int p = 0; p < NP; p += 2) {
        ulonglong2 v;
        v.x = acc[p];
        v.y = acc[p + 1];
        *(ulonglong2*)&tr[p * 2] = v;
    }
}

// ---------------- CSR aggregation: warp handles TWO nodes concurrently (double MLP) -------------

__device__ __forceinline__ void fma4(float4& a, float4 v, float w) {
    a.x += v.x * w; a.y += v.y * w; a.z += v.z * w; a.w += v.w * w;
}

template <int FO, int FOS, bool RS>
__global__ void __launch_bounds__(256) agg_kernel(
        const int* __restrict__ rp, const int2* __restrict__ meta,
        const float* __restrict__ t, const float* __restrict__ dis,
        const float* __restrict__ b, float* __restrict__ out,
        float* __restrict__ stats, int n) {
    __shared__ float ssum[RS ? FO : 1];
    __shared__ float ssq[RS ? FO : 1];
    if (RS) {
        for (int i = threadIdx.x; i < FO; i += blockDim.x) { ssum[i] = 0.0f; ssq[i] = 0.0f; }
        __syncthreads();
    }
    int lane = threadIdx.x & 31;
    int warp = (blockIdx.x * blockDim.x + threadIdx.x) >> 5;
    int nwarps = (gridDim.x * blockDim.x) >> 5;
    int cb = lane * 4;
    bool act = cb < FOS;
    float4 bias = make_float4(0.f, 0.f, 0.f, 0.f);
    if (cb + 0 < FO) bias.x = __ldg(&b[cb + 0]);
    if (cb + 1 < FO) bias.y = __ldg(&b[cb + 1]);
    if (cb + 2 < FO) bias.z = __ldg(&b[cb + 2]);
    if (cb + 3 < FO) bias.w = __ldg(&b[cb + 3]);
    float4 psum = make_float4(0.f, 0.f, 0.f, 0.f);
    float4 psq = make_float4(0.f, 0.f, 0.f, 0.f);

    for (int i0 = warp * 2; i0 < n; i0 += nwarps * 2) {
        int iA = i0;
        int iB = i0 + 1;
        bool hasB = iB < n;
        float dA = dis[iA];
        float d2A = dA * dA;
        float d2B = 0.0f;
        if (hasB) { float dB = dis[iB]; d2B = dB * dB; }
        float4 accA = bias, accB = bias;
        if (act) {
            float4 tv = __ldg((const float4*)&t[(size_t)iA * FOS + cb]);
            fma4(accA, tv, d2A);
            if (hasB) {
                float4 tw = __ldg((const float4*)&t[(size_t)iB * FOS + cb]);
                fma4(accB, tw, d2B);
            }
        }
        int jA = __ldg(&rp[iA]);
        int eA = __ldg(&rp[iA + 1]);
        int jB = hasB ? eA : 0;               // rp[iB] == rp[iA+1]
        int eB = hasB ? __ldg(&rp[iB + 1]) : 0;

        // align both streams to even index for int4 meta loads
        if (jA < eA && (jA & 1)) {
            int2 m = __ldg(&meta[jA]);
            if (act) fma4(accA, __ldg((const float4*)&t[(size_t)m.x * FOS + cb]), __int_as_float(m.y));
            jA++;
        }
        if (jB < eB && (jB & 1)) {
            int2 m = __ldg(&meta[jB]);
            if (act) fma4(accB, __ldg((const float4*)&t[(size_t)m.x * FOS + cb]), __int_as_float(m.y));
            jB++;
        }
        // interleaved main loop: 2 edges per node per iter -> 2 meta + 4 gathers in flight
        while (jA + 1 < eA && jB + 1 < eB) {
            int4 ma = __ldg((const int4*)&meta[jA]);
            int4 mb = __ldg((const int4*)&meta[jB]);
            if (act) {
                float4 a0 = __ldg((const float4*)&t[(size_t)ma.x * FOS + cb]);
                float4 a1 = __ldg((const float4*)&t[(size_t)ma.z * FOS + cb]);
                float4 b0 = __ldg((const float4*)&t[(size_t)mb.x * FOS + cb]);
                float4 b1 = __ldg((const float4*)&t[(size_t)mb.z * FOS + cb]);
                fma4(accA, a0, __int_as_float(ma.y));
                fma4(accA, a1, __int_as_float(ma.w));
                fma4(accB, b0, __int_as_float(mb.y));
                fma4(accB, b1, __int_as_float(mb.w));
            }
            jA += 2; jB += 2;
        }
        while (jA + 1 < eA) {
            int4 ma = __ldg((const int4*)&meta[jA]);
            if (act) {
                float4 a0 = __ldg((const float4*)&t[(size_t)ma.x * FOS + cb]);
                float4 a1 = __ldg((const float4*)&t[(size_t)ma.z * FOS + cb]);
                fma4(accA, a0, __int_as_float(ma.y));
                fma4(accA, a1, __int_as_float(ma.w));
            }
            jA += 2;
        }
        while (jB + 1 < eB) {
            int4 mb = __ldg((const int4*)&meta[jB]);
            if (act) {
                float4 b0 = __ldg((const float4*)&t[(size_t)mb.x * FOS + cb]);
                float4 b1 = __ldg((const float4*)&t[(size_t)mb.z * FOS + cb]);
                fma4(accB, b0, __int_as_float(mb.y));
                fma4(accB, b1, __int_as_float(mb.w));
            }
            jB += 2;
        }
        if (jA < eA) {
            int2 m = __ldg(&meta[jA]);
            if (act) fma4(accA, __ldg((const float4*)&t[(size_t)m.x * FOS + cb]), __int_as_float(m.y));
        }
        if (jB < eB) {
            int2 m = __ldg(&meta[jB]);
            if (act) fma4(accB, __ldg((const float4*)&t[(size_t)m.x * FOS + cb]), __int_as_float(m.y));
        }

        if (act) {
            if (RS) {
                accA.x = fmaxf(accA.x, 0.f); accA.y = fmaxf(accA.y, 0.f);
                accA.z = fmaxf(accA.z, 0.f); accA.w = fmaxf(accA.w, 0.f);
                psum.x += accA.x; psq.x += accA.x * accA.x;
                psum.y += accA.y; psq.y += accA.y * accA.y;
                psum.z += accA.z; psq.z += accA.z * accA.z;
                psum.w += accA.w; psq.w += accA.w * accA.w;
            }
            *(float4*)&out[(size_t)iA * FOS + cb] = accA;
            if (hasB) {
                if (RS) {
                    accB.x = fmaxf(accB.x, 0.f); accB.y = fmaxf(accB.y, 0.f);
                    accB.z = fmaxf(accB.z, 0.f); accB.w = fmaxf(accB.w, 0.f);
                    psum.x += accB.x; psq.x += accB.x * accB.x;
                    psum.y += accB.y; psq.y += accB.y * accB.y;
                    psum.z += accB.z; psq.z += accB.z * accB.z;
                    psum.w += accB.w; psq.w += accB.w * accB.w;
                }
                *(float4*)&out[(size_t)iB * FOS + cb] = accB;
            }
        }
    }

    if (RS) {
        if (act) {
            if (cb + 0 < FO) { atomicAdd(&ssum[cb + 0], psum.x); atomicAdd(&ssq[cb + 0], psq.x); }
            if (cb + 1 < FO) { atomicAdd(&ssum[cb + 1], psum.y); atomicAdd(&ssq[cb + 1], psq.y); }
            if (cb + 2 < FO) { atomicAdd(&ssum[cb + 2], psum.z); atomicAdd(&ssq[cb + 2], psq.z); }
            if (cb + 3 < FO) { atomicAdd(&ssum[cb + 3], psum.w); atomicAdd(&ssq[cb + 3], psq.w); }
        }
        __syncthreads();
        for (int i = threadIdx.x; i < FO; i += blockDim.x) {
            atomicAdd(&stats[i], ssum[i]);
            atomicAdd(&stats[128 + i], ssq[i]);
        }
    }
}

// ---------------- host driver ----------------

extern "C" void kernel_launch(void* const* d_in, const int* in_sizes, int n_in,
                              void* d_out, int out_size) {
    const float* x = (const float*)d_in[0];
    const int* edge = (const int*)d_in[1];   // int32 (JAX x64 disabled)
    const float* W1 = (const float*)d_in[2];
    const float* b1 = (const float*)d_in[3];
    const float* W2 = (const float*)d_in[4];
    const float* b2 = (const float*)d_in[5];
    const float* W3 = (const float*)d_in[6];
    const float* b3 = (const float*)d_in[7];
    const float* W4 = (const float*)d_in[8];
    const float* b4 = (const float*)d_in[9];
    const float* W5 = (const float*)d_in[10];
    const float* b5 = (const float*)d_in[11];
    const float* W6 = (const float*)d_in[12];
    const float* b6 = (const float*)d_in[13];
    const float* g1 = (const float*)d_in[14];
    const float* be1 = (const float*)d_in[15];
    const float* g2 = (const float*)d_in[16];
    const float* be2 = (const float*)d_in[17];
    const float* g3 = (const float*)d_in[18];
    const float* be3 = (const float*)d_in[19];
    const float* g4 = (const float*)d_in[20];
    const float* be4 = (const float*)d_in[21];

    int n = in_sizes[0] / 88;
    int E = in_sizes[1] / 2;
    const int* src = edge;
    const int* dst = edge + E;

    float *bufA, *bufB, *t, *dis, *sA, *sB;
    int *counts, *rp, *cursor;
    int2* meta;
    cudaGetSymbolAddress((void**)&bufA, g_bufA);
    cudaGetSymbolAddress((void**)&bufB, g_bufB);
    cudaGetSymbolAddress((void**)&t, g_t);
    cudaGetSymbolAddress((void**)&dis, g_dis);
    cudaGetSymbolAddress((void**)&counts, g_counts);
    cudaGetSymbolAddress((void**)&rp, g_rowptr);
    cudaGetSymbolAddress((void**)&cursor, g_cursor);
    cudaGetSymbolAddress((void**)&meta, g_meta);
    cudaGetSymbolAddress((void**)&sA, g_statsA);
    cudaGetSymbolAddress((void**)&sB, g_statsB);

    float* out = (float*)d_out;
    int gb = (n + 127) / 128;

    // CSR build, with gemm L1 hoisted to position 4 (depends only on x/W1) so ncu -s5 captures it
    zero_counts_kernel<<<(n + 255) / 256, 256>>>(counts, n);
    count_kernel<<<(E + 255) / 256, 256>>>(dst, counts, E);
    scan_kernel<<<1, 1024>>>(counts, rp, cursor, dis, n);
    gemm_kernel<88, 88, 70, 72, false, true><<<gb, 128>>>(x, W1, nullptr, nullptr, nullptr, sA, t, n);
    scatter_kernel<<<(E + 255) / 256, 256>>>(src, dst, dis, cursor, meta, E);

    // L1 agg: 88->70 (relu+bn -> statsA)
    agg_kernel<70, 72, true><<<1024, 256>>>(rp, meta, t, dis, b1, bufA, sA, n);
    // L2: 70->60 (affine from statsA/g1, relu+bn -> statsB)
    gemm_kernel<70, 72, 60, 60, true, true><<<gb, 128>>>(bufA, W2, g1, be1, sA, sB, t, n);
    agg_kernel<60, 60, true><<<1024, 256>>>(rp, meta, t, dis, b2, bufB, sB, n);
    // L3: 60->50 (affine from statsB/g2, no bn)
    gemm_kernel<60, 60, 50, 52, true, false><<<gb, 128>>>(bufB, W3, g2, be2, sB, nullptr, t, n);
    agg_kernel<50, 52, false><<<1024, 256>>>(rp, meta, t, dis, b3, bufA, nullptr, n);
    // L4: 50->60 (no affine, relu+bn -> statsA)
    gemm_kernel<50, 52, 60, 60, false, true><<<gb, 128>>>(bufA, W4, nullptr, nullptr, nullptr, sA, t, n);
    agg_kernel<60, 60, true><<<1024, 256>>>(rp, meta, t, dis, b4, bufB, sA, n);
    // L5: 60->70 (affine from statsA/g3, relu+bn -> statsB)
    gemm_kernel<60, 60, 70, 72, true, true><<<gb, 128>>>(bufB, W5, g3, be3, sA, sB, t, n);
    agg_kernel<70, 72, true><<<1024, 256>>>(rp, meta, t, dis, b5, bufA, sB, n);
    // L6: 70->88 (affine from statsB/g4, no bn) -> out
    gemm_kernel<70, 72, 88, 88, true, false><<<gb, 128>>>(bufA, W6, g4, be4, sB, nullptr, t, n);
    agg_kernel<88, 88, false><<<1024, 256>>>(rp, meta, t, dis, b6, out, nullptr, n);
}

// round 8
// speedup vs baseline: 2.1036x; 1.0740x over previous
#include <cuda_runtime.h>
#include <cuda_fp16.h>

#define NMAX 50000
#define EMAX 800000

// ---- scratch (device globals; no allocation allowed) ----
__device__ __align__(16) float g_bufA[NMAX * 96];
__device__ __align__(16) float g_bufB[NMAX * 96];
__device__ __align__(16) __half g_t[NMAX * 96];   // fp16 transformed features
__device__ float g_dis[NMAX];
__device__ int   g_counts[NMAX];
__device__ int   g_rowptr[NMAX + 1];
__device__ int   g_cursor[NMAX];
__device__ __align__(16) int2 g_meta[EMAX];  // (src, bitcast(weight)), 16B-aligned for int4 loads
__device__ float g_statsA[256];              // [0..128) sum, [128..256) sumsq
__device__ float g_statsB[256];

// ---------------- CSR build ----------------

__global__ void zero_counts_kernel(int* counts, int n) {
    int i = blockIdx.x * blockDim.x + threadIdx.x;
    if (i < n) counts[i] = 0;
}

__global__ void count_kernel(const int* __restrict__ dst, int* counts, int E) {
    int e = blockIdx.x * blockDim.x + threadIdx.x;
    if (e < E) atomicAdd(&counts[dst[e]], 1);
}

__global__ void scan_kernel(const int* __restrict__ counts, int* __restrict__ row_ptr,
                            int* __restrict__ cursor, float* __restrict__ dis, int n) {
    __shared__ int part[1024];
    int tid = threadIdx.x;
    int chunk = (n + 1023) / 1024;
    int beg = tid * chunk;
    int end = min(beg + chunk, n);
    int s = 0;
    for (int i = beg; i < end; i++) s += counts[i];
    part[tid] = s;
    __syncthreads();
    for (int off = 1; off < 1024; off <<= 1) {
        int v = part[tid];
        int add = (tid >= off) ? part[tid - off] : 0;
        __syncthreads();
        part[tid] = v + add;
        __syncthreads();
    }
    int run = (tid > 0) ? part[tid - 1] : 0;
    for (int i = beg; i < end; i++) {
        int c = counts[i];
        row_ptr[i] = run;
        cursor[i] = run;
        dis[i] = rsqrtf((float)c + 1.0f);
        run += c;
    }
    if (tid == 1023) row_ptr[n] = part[1023];
}

__global__ void scatter_kernel(const int* __restrict__ src, const int* __restrict__ dst,
                               const float* __restrict__ dis,
                               int* __restrict__ cursor, int2* __restrict__ meta, int E) {
    int e = blockIdx.x * blockDim.x + threadIdx.x;
    if (e >= E) return;
    int s = src[e];
    int d = dst[e];
    int pos = atomicAdd(&cursor[d], 1);
    meta[pos] = make_int2(s, __float_as_int(dis[s] * dis[d]));
}

// ---------------- fused GEMM: bn-finalize + affine-fold + gemm ----------------------------------
// 256 threads / 128 rows per block: thread (row, half) computes alternating float4 column groups.
// fp32 accumulate (fma.rn.f32x2), fp16 store.

template <int FI, int FIS, int FO, int FOS, bool AFF, bool ZERO>
__global__ void __launch_bounds__(256) gemm_kernel(
        const float* __restrict__ x, const float* __restrict__ W,
        const float* __restrict__ g, const float* __restrict__ be,
        const float* __restrict__ stats_prev, float* __restrict__ stats_cur,
        __half* __restrict__ t, int n) {
    __shared__ __align__(16) float sW[FIS * FOS];
    __shared__ __align__(16) float s_tc[FOS];
    __shared__ float s_sc[96], s_sh[96];
    int tid = threadIdx.x;

    if (AFF) {
        if (tid < FI) {
            float inv_n = 1.0f / (float)n;
            float mu = stats_prev[tid] * inv_n;
            float var = stats_prev[128 + tid] * inv_n - mu * mu;
            float s = g[tid] * rsqrtf(var + 1e-5f);
            s_sc[tid] = s;
            s_sh[tid] = be[tid] - mu * s;
        }
        __syncthreads();
    }
    if (ZERO && blockIdx.x == 0) stats_cur[tid] = 0.0f;   // 256 threads cover sum+sumsq
    for (int idx = tid; idx < FIS * FOS; idx += 256) {
        int k = idx / FOS;
        int c = idx - k * FOS;
        float v = 0.0f;
        if (k < FI && c < FO) {
            v = __ldg(&W[k * FO + c]);
            if (AFF) v *= s_sc[k];
        }
        sW[idx] = v;
    }
    if (tid < FOS) {
        float tv = 0.0f;
        if (AFF && tid < FO) {
#pragma unroll 8
            for (int k = 0; k < FI; k++) tv += s_sh[k] * __ldg(&W[k * FO + tid]);
        }
        s_tc[tid] = tv;
    }
    __syncthreads();

    int row = blockIdx.x * 128 + (tid >> 1);
    int h = tid & 1;
    if (row >= n) return;
    const float4* xr = (const float4*)(x + (size_t)row * FIS);
    constexpr int NG = FOS / 4;           // float4 column groups
    constexpr int MG = (NG + 1) / 2;      // groups per thread (worst case, h=0)
    unsigned long long acc[MG * 2];
    const unsigned long long* tcp = (const unsigned long long*)s_tc;
#pragma unroll
    for (int gi = 0; gi < MG; gi++) {
        int gg = h + 2 * gi;
        if (gg < NG) {
            acc[2 * gi]     = tcp[gg * 2];
            acc[2 * gi + 1] = tcp[gg * 2 + 1];
        }
    }
#pragma unroll 1
    for (int k4 = 0; k4 < FIS / 4; k4++) {
        float4 xv = __ldg(&xr[k4]);
#pragma unroll
        for (int j = 0; j < 4; j++) {
            float xk = (j == 0) ? xv.x : (j == 1) ? xv.y : (j == 2) ? xv.z : xv.w;
            unsigned long long a2;
            asm("mov.b64 %0, {%1, %1};" : "=l"(a2) : "r"(__float_as_uint(xk)));
            const float* wr = &sW[(k4 * 4 + j) * FOS];
#pragma unroll
            for (int gi = 0; gi < MG; gi++) {
                int gg = h + 2 * gi;
                if (gg < NG) {
                    ulonglong2 w2 = *(const ulonglong2*)(wr + gg * 4);
                    asm("fma.rn.f32x2 %0, %1, %2, %0;" : "+l"(acc[2 * gi]) : "l"(a2), "l"(w2.x));
                    asm("fma.rn.f32x2 %0, %1, %2, %0;" : "+l"(acc[2 * gi + 1]) : "l"(a2), "l"(w2.y));
                }
            }
        }
    }
    __half* tr = t + (size_t)row * FOS;
#pragma unroll
    for (int gi = 0; gi < MG; gi++) {
        int gg = h + 2 * gi;
        if (gg < NG) {
            float2 f0 = *(const float2*)&acc[2 * gi];
            float2 f1 = *(const float2*)&acc[2 * gi + 1];
            __half2 h0 = __floats2half2_rn(f0.x, f0.y);
            __half2 h1 = __floats2half2_rn(f1.x, f1.y);
            uint2 u;
            u.x = *(const unsigned*)&h0;
            u.y = *(const unsigned*)&h1;
            *(uint2*)&tr[gg * 4] = u;
        }
    }
}

// ---------------- CSR aggregation: warp handles TWO nodes, fp16 gathers ----------------

__device__ __forceinline__ void fma4(float4& a, float4 v, float w) {
    a.x += v.x * w; a.y += v.y * w; a.z += v.z * w; a.w += v.w * w;
}

__device__ __forceinline__ float4 ld_t4(const __half* __restrict__ t, size_t off) {
    uint2 u = __ldg((const uint2*)(t + off));
    __half2 h0 = *reinterpret_cast<__half2*>(&u.x);
    __half2 h1 = *reinterpret_cast<__half2*>(&u.y);
    float2 f0 = __half22float2(h0);
    float2 f1 = __half22float2(h1);
    return make_float4(f0.x, f0.y, f1.x, f1.y);
}

template <int FO, int FOS, bool RS>
__global__ void __launch_bounds__(256) agg_kernel(
        const int* __restrict__ rp, const int2* __restrict__ meta,
        const __half* __restrict__ t, const float* __restrict__ dis,
        const float* __restrict__ b, float* __restrict__ out,
        float* __restrict__ stats, int n) {
    __shared__ float ssum[RS ? FO : 1];
    __shared__ float ssq[RS ? FO : 1];
    if (RS) {
        for (int i = threadIdx.x; i < FO; i += blockDim.x) { ssum[i] = 0.0f; ssq[i] = 0.0f; }
        __syncthreads();
    }
    int lane = threadIdx.x & 31;
    int warp = (blockIdx.x * blockDim.x + threadIdx.x) >> 5;
    int nwarps = (gridDim.x * blockDim.x) >> 5;
    int cb = lane * 4;
    bool act = cb < FOS;
    float4 bias = make_float4(0.f, 0.f, 0.f, 0.f);
    if (cb + 0 < FO) bias.x = __ldg(&b[cb + 0]);
    if (cb + 1 < FO) bias.y = __ldg(&b[cb + 1]);
    if (cb + 2 < FO) bias.z = __ldg(&b[cb + 2]);
    if (cb + 3 < FO) bias.w = __ldg(&b[cb + 3]);
    float4 psum = make_float4(0.f, 0.f, 0.f, 0.f);
    float4 psq = make_float4(0.f, 0.f, 0.f, 0.f);

    for (int i0 = warp * 2; i0 < n; i0 += nwarps * 2) {
        int iA = i0;
        int iB = i0 + 1;
        bool hasB = iB < n;
        float dA = dis[iA];
        float d2A = dA * dA;
        float d2B = 0.0f;
        if (hasB) { float dB = dis[iB]; d2B = dB * dB; }
        float4 accA = bias, accB = bias;
        if (act) {
            fma4(accA, ld_t4(t, (size_t)iA * FOS + cb), d2A);
            if (hasB) fma4(accB, ld_t4(t, (size_t)iB * FOS + cb), d2B);
        }
        int jA = __ldg(&rp[iA]);
        int eA = __ldg(&rp[iA + 1]);
        int jB = hasB ? eA : 0;
        int eB = hasB ? __ldg(&rp[iB + 1]) : 0;

        if (jA < eA && (jA & 1)) {
            int2 m = __ldg(&meta[jA]);
            if (act) fma4(accA, ld_t4(t, (size_t)m.x * FOS + cb), __int_as_float(m.y));
            jA++;
        }
        if (jB < eB && (jB & 1)) {
            int2 m = __ldg(&meta[jB]);
            if (act) fma4(accB, ld_t4(t, (size_t)m.x * FOS + cb), __int_as_float(m.y));
            jB++;
        }
        while (jA + 1 < eA && jB + 1 < eB) {
            int4 ma = __ldg((const int4*)&meta[jA]);
            int4 mb = __ldg((const int4*)&meta[jB]);
            if (act) {
                float4 a0 = ld_t4(t, (size_t)ma.x * FOS + cb);
                float4 a1 = ld_t4(t, (size_t)ma.z * FOS + cb);
                float4 b0 = ld_t4(t, (size_t)mb.x * FOS + cb);
                float4 b1 = ld_t4(t, (size_t)mb.z * FOS + cb);
                fma4(accA, a0, __int_as_float(ma.y));
                fma4(accA, a1, __int_as_float(ma.w));
                fma4(accB, b0, __int_as_float(mb.y));
                fma4(accB, b1, __int_as_float(mb.w));
            }
            jA += 2; jB += 2;
        }
        while (jA + 1 < eA) {
            int4 ma = __ldg((const int4*)&meta[jA]);
            if (act) {
                fma4(accA, ld_t4(t, (size_t)ma.x * FOS + cb), __int_as_float(ma.y));
                fma4(accA, ld_t4(t, (size_t)ma.z * FOS + cb), __int_as_float(ma.w));
            }
            jA += 2;
        }
        while (jB + 1 < eB) {
            int4 mb = __ldg((const int4*)&meta[jB]);
            if (act) {
                fma4(accB, ld_t4(t, (size_t)mb.x * FOS + cb), __int_as_float(mb.y));
                fma4(accB, ld_t4(t, (size_t)mb.z * FOS + cb), __int_as_float(mb.w));
            }
            jB += 2;
        }
        if (jA < eA) {
            int2 m = __ldg(&meta[jA]);
            if (act) fma4(accA, ld_t4(t, (size_t)m.x * FOS + cb), __int_as_float(m.y));
        }
        if (jB < eB) {
            int2 m = __ldg(&meta[jB]);
            if (act) fma4(accB, ld_t4(t, (size_t)m.x * FOS + cb), __int_as_float(m.y));
        }

        if (act) {
            if (RS) {
                accA.x = fmaxf(accA.x, 0.f); accA.y = fmaxf(accA.y, 0.f);
                accA.z = fmaxf(accA.z, 0.f); accA.w = fmaxf(accA.w, 0.f);
                psum.x += accA.x; psq.x += accA.x * accA.x;
                psum.y += accA.y; psq.y += accA.y * accA.y;
                psum.z += accA.z; psq.z += accA.z * accA.z;
                psum.w += accA.w; psq.w += accA.w * accA.w;
            }
            *(float4*)&out[(size_t)iA * FOS + cb] = accA;
            if (hasB) {
                if (RS) {
                    accB.x = fmaxf(accB.x, 0.f); accB.y = fmaxf(accB.y, 0.f);
                    accB.z = fmaxf(accB.z, 0.f); accB.w = fmaxf(accB.w, 0.f);
                    psum.x += accB.x; psq.x += accB.x * accB.x;
                    psum.y += accB.y; psq.y += accB.y * accB.y;
                    psum.z += accB.z; psq.z += accB.z * accB.z;
                    psum.w += accB.w; psq.w += accB.w * accB.w;
                }
                *(float4*)&out[(size_t)iB * FOS + cb] = accB;
            }
        }
    }

    if (RS) {
        if (act) {
            if (cb + 0 < FO) { atomicAdd(&ssum[cb + 0], psum.x); atomicAdd(&ssq[cb + 0], psq.x); }
            if (cb + 1 < FO) { atomicAdd(&ssum[cb + 1], psum.y); atomicAdd(&ssq[cb + 1], psq.y); }
            if (cb + 2 < FO) { atomicAdd(&ssum[cb + 2], psum.z); atomicAdd(&ssq[cb + 2], psq.z); }
            if (cb + 3 < FO) { atomicAdd(&ssum[cb + 3], psum.w); atomicAdd(&ssq[cb + 3], psq.w); }
        }
        __syncthreads();
        for (int i = threadIdx.x; i < FO; i += blockDim.x) {
            atomicAdd(&stats[i], ssum[i]);
            atomicAdd(&stats[128 + i], ssq[i]);
        }
    }
}

// ---------------- host driver ----------------

extern "C" void kernel_launch(void* const* d_in, const int* in_sizes, int n_in,
                              void* d_out, int out_size) {
    const float* x = (const float*)d_in[0];
    const int* edge = (const int*)d_in[1];   // int32 (JAX x64 disabled)
    const float* W1 = (const float*)d_in[2];
    const float* b1 = (const float*)d_in[3];
    const float* W2 = (const float*)d_in[4];
    const float* b2 = (const float*)d_in[5];
    const float* W3 = (const float*)d_in[6];
    const float* b3 = (const float*)d_in[7];
    const float* W4 = (const float*)d_in[8];
    const float* b4 = (const float*)d_in[9];
    const float* W5 = (const float*)d_in[10];
    const float* b5 = (const float*)d_in[11];
    const float* W6 = (const float*)d_in[12];
    const float* b6 = (const float*)d_in[13];
    const float* g1 = (const float*)d_in[14];
    const float* be1 = (const float*)d_in[15];
    const float* g2 = (const float*)d_in[16];
    const float* be2 = (const float*)d_in[17];
    const float* g3 = (const float*)d_in[18];
    const float* be3 = (const float*)d_in[19];
    const float* g4 = (const float*)d_in[20];
    const float* be4 = (const float*)d_in[21];

    int n = in_sizes[0] / 88;
    int E = in_sizes[1] / 2;
    const int* src = edge;
    const int* dst = edge + E;

    float *bufA, *bufB, *dis, *sA, *sB;
    __half* t;
    int *counts, *rp, *cursor;
    int2* meta;
    cudaGetSymbolAddress((void**)&bufA, g_bufA);
    cudaGetSymbolAddress((void**)&bufB, g_bufB);
    cudaGetSymbolAddress((void**)&t, g_t);
    cudaGetSymbolAddress((void**)&dis, g_dis);
    cudaGetSymbolAddress((void**)&counts, g_counts);
    cudaGetSymbolAddress((void**)&rp, g_rowptr);
    cudaGetSymbolAddress((void**)&cursor, g_cursor);
    cudaGetSymbolAddress((void**)&meta, g_meta);
    cudaGetSymbolAddress((void**)&sA, g_statsA);
    cudaGetSymbolAddress((void**)&sB, g_statsB);

    float* out = (float*)d_out;
    int gb = (n + 127) / 128;

    zero_counts_kernel<<<(n + 255) / 256, 256>>>(counts, n);
    count_kernel<<<(E + 255) / 256, 256>>>(dst, counts, E);
    scan_kernel<<<1, 1024>>>(counts, rp, cursor, dis, n);
    gemm_kernel<88, 88, 70, 72, false, true><<<gb, 256>>>(x, W1, nullptr, nullptr, nullptr, sA, t, n);
    scatter_kernel<<<(E + 255) / 256, 256>>>(src, dst, dis, cursor, meta, E);

    // L1 agg: 88->70 (relu+bn -> statsA)
    agg_kernel<70, 72, true><<<1024, 256>>>(rp, meta, t, dis, b1, bufA, sA, n);
    // L2: 70->60
    gemm_kernel<70, 72, 60, 60, true, true><<<gb, 256>>>(bufA, W2, g1, be1, sA, sB, t, n);
    agg_kernel<60, 60, true><<<1024, 256>>>(rp, meta, t, dis, b2, bufB, sB, n);
    // L3: 60->50
    gemm_kernel<60, 60, 50, 52, true, false><<<gb, 256>>>(bufB, W3, g2, be2, sB, nullptr, t, n);
    agg_kernel<50, 52, false><<<1024, 256>>>(rp, meta, t, dis, b3, bufA, nullptr, n);
    // L4: 50->60
    gemm_kernel<50, 52, 60, 60, false, true><<<gb, 256>>>(bufA, W4, nullptr, nullptr, nullptr, sA, t, n);
    agg_kernel<60, 60, true><<<1024, 256>>>(rp, meta, t, dis, b4, bufB, sA, n);
    // L5: 60->70
    gemm_kernel<60, 60, 70, 72, true, true><<<gb, 256>>>(bufB, W5, g3, be3, sA, sB, t, n);
    agg_kernel<70, 72, true><<<1024, 256>>>(rp, meta, t, dis, b5, bufA, sB, n);
    // L6: 70->88 -> out
    gemm_kernel<70, 72, 88, 88, true, false><<<gb, 256>>>(bufA, W6, g4, be4, sB, nullptr, t, n);
    agg_kernel<88, 88, false><<<1024, 256>>>(rp, meta, t, dis, b6, out, nullptr, n);
}

// round 9
// speedup vs baseline: 2.1368x; 1.0158x over previous
#include <cuda_runtime.h>
#include <cuda_fp16.h>

#define NMAX 50000
#define EMAX 800000

// ---- scratch (device globals; no allocation allowed) ----
__device__ __align__(16) float g_bufA[NMAX * 96];
__device__ __align__(16) float g_bufB[NMAX * 96];
__device__ __align__(16) float g_t[NMAX * 96];
__device__ float g_dis[NMAX];
__device__ int   g_counts[NMAX];
__device__ int   g_rowptr[NMAX + 1];
__device__ int   g_cursor[NMAX];
__device__ __align__(16) int2 g_meta[EMAX];  // (src, bitcast(weight))
__device__ float g_statsA[256];              // [0..128) sum, [128..256) sumsq
__device__ float g_statsB[256];

// ---------------- CSR build ----------------

__global__ void zero_counts_kernel(int* counts, int n) {
    int i = blockIdx.x * blockDim.x + threadIdx.x;
    if (i < n) counts[i] = 0;
}

__global__ void count_kernel(const int* __restrict__ dst, int* counts, int E) {
    int e = blockIdx.x * blockDim.x + threadIdx.x;
    if (e < E) atomicAdd(&counts[dst[e]], 1);
}

__global__ void scan_kernel(const int* __restrict__ counts, int* __restrict__ row_ptr,
                            int* __restrict__ cursor, float* __restrict__ dis, int n) {
    __shared__ int part[1024];
    int tid = threadIdx.x;
    int chunk = (n + 1023) / 1024;
    int beg = tid * chunk;
    int end = min(beg + chunk, n);
    int s = 0;
    for (int i = beg; i < end; i++) s += counts[i];
    part[tid] = s;
    __syncthreads();
    for (int off = 1; off < 1024; off <<= 1) {
        int v = part[tid];
        int add = (tid >= off) ? part[tid - off] : 0;
        __syncthreads();
        part[tid] = v + add;
        __syncthreads();
    }
    int run = (tid > 0) ? part[tid - 1] : 0;
    for (int i = beg; i < end; i++) {
        int c = counts[i];
        row_ptr[i] = run;
        cursor[i] = run;
        dis[i] = rsqrtf((float)c + 1.0f);
        run += c;
    }
    if (tid == 1023) row_ptr[n] = part[1023];
}

__global__ void scatter_kernel(const int* __restrict__ src, const int* __restrict__ dst,
                               const float* __restrict__ dis,
                               int* __restrict__ cursor, int2* __restrict__ meta, int E) {
    int e = blockIdx.x * blockDim.x + threadIdx.x;
    if (e >= E) return;
    int s = src[e];
    int d = dst[e];
    int pos = atomicAdd(&cursor[d], 1);
    meta[pos] = make_int2(s, __float_as_int(dis[s] * dis[d]));
}

// ---------------- fused GEMM: bn-finalize + affine-fold + gemm (fma.rn.f32x2) --------------------
// 256 threads / 128 rows per block: thread (row, half) computes alternating float4 column groups.

template <int FI, int FIS, int FO, int FOS, bool AFF, bool ZERO>
__global__ void __launch_bounds__(256) gemm_kernel(
        const float* __restrict__ x, const float* __restrict__ W,
        const float* __restrict__ g, const float* __restrict__ be,
        const float* __restrict__ stats_prev, float* __restrict__ stats_cur,
        float* __restrict__ t, int n) {
    __shared__ __align__(16) float sW[FIS * FOS];
    __shared__ __align__(16) float s_tc[FOS];
    __shared__ float s_sc[96], s_sh[96];
    int tid = threadIdx.x;

    if (AFF) {
        if (tid < FI) {
            float inv_n = 1.0f / (float)n;
            float mu = stats_prev[tid] * inv_n;
            float var = stats_prev[128 + tid] * inv_n - mu * mu;
            float s = g[tid] * rsqrtf(var + 1e-5f);
            s_sc[tid] = s;
            s_sh[tid] = be[tid] - mu * s;
        }
        __syncthreads();
    }
    if (ZERO && blockIdx.x == 0) stats_cur[tid] = 0.0f;   // 256 threads cover sum+sumsq
    for (int idx = tid; idx < FIS * FOS; idx += 256) {
        int k = idx / FOS;
        int c = idx - k * FOS;
        float v = 0.0f;
        if (k < FI && c < FO) {
            v = __ldg(&W[k * FO + c]);
            if (AFF) v *= s_sc[k];
        }
        sW[idx] = v;
    }
    if (tid < FOS) {
        float tv = 0.0f;
        if (AFF && tid < FO) {
#pragma unroll 8
            for (int k = 0; k < FI; k++) tv += s_sh[k] * __ldg(&W[k * FO + tid]);
        }
        s_tc[tid] = tv;
    }
    __syncthreads();

    int row = blockIdx.x * 128 + (tid >> 1);
    int h = tid & 1;
    if (row >= n) return;
    const float4* xr = (const float4*)(x + (size_t)row * FIS);
    constexpr int NG = FOS / 4;           // float4 column groups
    constexpr int MG = (NG + 1) / 2;      // groups per thread (worst case, h=0)
    unsigned long long acc[MG * 2];
    const unsigned long long* tcp = (const unsigned long long*)s_tc;
#pragma unroll
    for (int gi = 0; gi < MG; gi++) {
        int gg = h + 2 * gi;
        if (gg < NG) {
            acc[2 * gi]     = tcp[gg * 2];
            acc[2 * gi + 1] = tcp[gg * 2 + 1];
        }
    }
#pragma unroll 1
    for (int k4 = 0; k4 < FIS / 4; k4++) {
        float4 xv = __ldg(&xr[k4]);
#pragma unroll
        for (int j = 0; j < 4; j++) {
            float xk = (j == 0) ? xv.x : (j == 1) ? xv.y : (j == 2) ? xv.z : xv.w;
            unsigned long long a2;
            asm("mov.b64 %0, {%1, %1};" : "=l"(a2) : "r"(__float_as_uint(xk)));
            const float* wr = &sW[(k4 * 4 + j) * FOS];
#pragma unroll
            for (int gi = 0; gi < MG; gi++) {
                int gg = h + 2 * gi;
                if (gg < NG) {
                    ulonglong2 w2 = *(const ulonglong2*)(wr + gg * 4);
                    asm("fma.rn.f32x2 %0, %1, %2, %0;" : "+l"(acc[2 * gi]) : "l"(a2), "l"(w2.x));
                    asm("fma.rn.f32x2 %0, %1, %2, %0;" : "+l"(acc[2 * gi + 1]) : "l"(a2), "l"(w2.y));
                }
            }
        }
    }
    float* tr = t + (size_t)row * FOS;
#pragma unroll
    for (int gi = 0; gi < MG; gi++) {
        int gg = h + 2 * gi;
        if (gg < NG) {
            ulonglong2 v;
            v.x = acc[2 * gi];
            v.y = acc[2 * gi + 1];
            *(ulonglong2*)&tr[gg * 4] = v;
        }
    }
}

// ---------------- CSR aggregation: warp per node, lane-parallel meta + shfl broadcast -----------
// One coalesced meta load per 32-edge chunk, then up to 32 independent gathers in flight.

__device__ __forceinline__ void fma4(float4& a, float4 v, float w) {
    a.x += v.x * w; a.y += v.y * w; a.z += v.z * w; a.w += v.w * w;
}

template <int FO, int FOS, bool RS>
__global__ void __launch_bounds__(256) agg_kernel(
        const int* __restrict__ rp, const int2* __restrict__ meta,
        const float* __restrict__ t, const float* __restrict__ dis,
        const float* __restrict__ b, float* __restrict__ out,
        float* __restrict__ stats, int n) {
    __shared__ float ssum[RS ? FO : 1];
    __shared__ float ssq[RS ? FO : 1];
    if (RS) {
        for (int i = threadIdx.x; i < FO; i += blockDim.x) { ssum[i] = 0.0f; ssq[i] = 0.0f; }
        __syncthreads();
    }
    int lane = threadIdx.x & 31;
    int warp = (blockIdx.x * blockDim.x + threadIdx.x) >> 5;
    int nwarps = (gridDim.x * blockDim.x) >> 5;
    int cb = lane * 4;
    bool act = cb < FOS;
    float4 bias = make_float4(0.f, 0.f, 0.f, 0.f);
    if (cb + 0 < FO) bias.x = __ldg(&b[cb + 0]);
    if (cb + 1 < FO) bias.y = __ldg(&b[cb + 1]);
    if (cb + 2 < FO) bias.z = __ldg(&b[cb + 2]);
    if (cb + 3 < FO) bias.w = __ldg(&b[cb + 3]);
    float4 psum = make_float4(0.f, 0.f, 0.f, 0.f);
    float4 psq = make_float4(0.f, 0.f, 0.f, 0.f);

    for (int i = warp; i < n; i += nwarps) {
        float dd = dis[i];
        float d2 = dd * dd;
        float4 acc = bias;
        if (act) fma4(acc, __ldg((const float4*)&t[(size_t)i * FOS + cb]), d2);

        int beg = __ldg(&rp[i]);
        int end = __ldg(&rp[i + 1]);
        for (int base = beg; base < end; base += 32) {
            int rem = min(32, end - base);
            int2 m = make_int2(0, 0);
            if (lane < rem) m = __ldg(&meta[base + lane]);
            int k = 0;
#pragma unroll 1
            for (; k + 4 <= rem; k += 4) {
                int s0 = __shfl_sync(0xffffffffu, m.x, k);
                int w0 = __shfl_sync(0xffffffffu, m.y, k);
                int s1 = __shfl_sync(0xffffffffu, m.x, k + 1);
                int w1 = __shfl_sync(0xffffffffu, m.y, k + 1);
                int s2 = __shfl_sync(0xffffffffu, m.x, k + 2);
                int w2 = __shfl_sync(0xffffffffu, m.y, k + 2);
                int s3 = __shfl_sync(0xffffffffu, m.x, k + 3);
                int w3 = __shfl_sync(0xffffffffu, m.y, k + 3);
                if (act) {
                    float4 v0 = __ldg((const float4*)&t[(size_t)s0 * FOS + cb]);
                    float4 v1 = __ldg((const float4*)&t[(size_t)s1 * FOS + cb]);
                    float4 v2 = __ldg((const float4*)&t[(size_t)s2 * FOS + cb]);
                    float4 v3 = __ldg((const float4*)&t[(size_t)s3 * FOS + cb]);
                    fma4(acc, v0, __int_as_float(w0));
                    fma4(acc, v1, __int_as_float(w1));
                    fma4(acc, v2, __int_as_float(w2));
                    fma4(acc, v3, __int_as_float(w3));
                }
            }
#pragma unroll 1
            for (; k < rem; k++) {
                int s0 = __shfl_sync(0xffffffffu, m.x, k);
                int w0 = __shfl_sync(0xffffffffu, m.y, k);
                if (act) {
                    float4 v0 = __ldg((const float4*)&t[(size_t)s0 * FOS + cb]);
                    fma4(acc, v0, __int_as_float(w0));
                }
            }
        }

        if (act) {
            if (RS) {
                acc.x = fmaxf(acc.x, 0.f); acc.y = fmaxf(acc.y, 0.f);
                acc.z = fmaxf(acc.z, 0.f); acc.w = fmaxf(acc.w, 0.f);
                psum.x += acc.x; psq.x += acc.x * acc.x;
                psum.y += acc.y; psq.y += acc.y * acc.y;
                psum.z += acc.z; psq.z += acc.z * acc.z;
                psum.w += acc.w; psq.w += acc.w * acc.w;
            }
            *(float4*)&out[(size_t)i * FOS + cb] = acc;
        }
    }

    if (RS) {
        if (act) {
            if (cb + 0 < FO) { atomicAdd(&ssum[cb + 0], psum.x); atomicAdd(&ssq[cb + 0], psq.x); }
            if (cb + 1 < FO) { atomicAdd(&ssum[cb + 1], psum.y); atomicAdd(&ssq[cb + 1], psq.y); }
            if (cb + 2 < FO) { atomicAdd(&ssum[cb + 2], psum.z); atomicAdd(&ssq[cb + 2], psq.z); }
            if (cb + 3 < FO) { atomicAdd(&ssum[cb + 3], psum.w); atomicAdd(&ssq[cb + 3], psq.w); }
        }
        __syncthreads();
        for (int i = threadIdx.x; i < FO; i += blockDim.x) {
            atomicAdd(&stats[i], ssum[i]);
            atomicAdd(&stats[128 + i], ssq[i]);
        }
    }
}

// ---------------- host driver ----------------

extern "C" void kernel_launch(void* const* d_in, const int* in_sizes, int n_in,
                              void* d_out, int out_size) {
    const float* x = (const float*)d_in[0];
    const int* edge = (const int*)d_in[1];   // int32 (JAX x64 disabled)
    const float* W1 = (const float*)d_in[2];
    const float* b1 = (const float*)d_in[3];
    const float* W2 = (const float*)d_in[4];
    const float* b2 = (const float*)d_in[5];
    const float* W3 = (const float*)d_in[6];
    const float* b3 = (const float*)d_in[7];
    const float* W4 = (const float*)d_in[8];
    const float* b4 = (const float*)d_in[9];
    const float* W5 = (const float*)d_in[10];
    const float* b5 = (const float*)d_in[11];
    const float* W6 = (const float*)d_in[12];
    const float* b6 = (const float*)d_in[13];
    const float* g1 = (const float*)d_in[14];
    const float* be1 = (const float*)d_in[15];
    const float* g2 = (const float*)d_in[16];
    const float* be2 = (const float*)d_in[17];
    const float* g3 = (const float*)d_in[18];
    const float* be3 = (const float*)d_in[19];
    const float* g4 = (const float*)d_in[20];
    const float* be4 = (const float*)d_in[21];

    int n = in_sizes[0] / 88;
    int E = in_sizes[1] / 2;
    const int* src = edge;
    const int* dst = edge + E;

    float *bufA, *bufB, *t, *dis, *sA, *sB;
    int *counts, *rp, *cursor;
    int2* meta;
    cudaGetSymbolAddress((void**)&bufA, g_bufA);
    cudaGetSymbolAddress((void**)&bufB, g_bufB);
    cudaGetSymbolAddress((void**)&t, g_t);
    cudaGetSymbolAddress((void**)&dis, g_dis);
    cudaGetSymbolAddress((void**)&counts, g_counts);
    cudaGetSymbolAddress((void**)&rp, g_rowptr);
    cudaGetSymbolAddress((void**)&cursor, g_cursor);
    cudaGetSymbolAddress((void**)&meta, g_meta);
    cudaGetSymbolAddress((void**)&sA, g_statsA);
    cudaGetSymbolAddress((void**)&sB, g_statsB);

    float* out = (float*)d_out;
    int gb = (n + 127) / 128;

    zero_counts_kernel<<<(n + 255) / 256, 256>>>(counts, n);
    count_kernel<<<(E + 255) / 256, 256>>>(dst, counts, E);
    scan_kernel<<<1, 1024>>>(counts, rp, cursor, dis, n);
    gemm_kernel<88, 88, 70, 72, false, true><<<gb, 256>>>(x, W1, nullptr, nullptr, nullptr, sA, t, n);
    scatter_kernel<<<(E + 255) / 256, 256>>>(src, dst, dis, cursor, meta, E);

    // L1 agg: 88->70 (relu+bn -> statsA)
    agg_kernel<70, 72, true><<<1024, 256>>>(rp, meta, t, dis, b1, bufA, sA, n);
    // L2: 70->60
    gemm_kernel<70, 72, 60, 60, true, true><<<gb, 256>>>(bufA, W2, g1, be1, sA, sB, t, n);
    agg_kernel<60, 60, true><<<1024, 256>>>(rp, meta, t, dis, b2, bufB, sB, n);
    // L3: 60->50
    gemm_kernel<60, 60, 50, 52, true, false><<<gb, 256>>>(bufB, W3, g2, be2, sB, nullptr, t, n);
    agg_kernel<50, 52, false><<<1024, 256>>>(rp, meta, t, dis, b3, bufA, nullptr, n);
    // L4: 50->60
    gemm_kernel<50, 52, 60, 60, false, true><<<gb, 256>>>(bufA, W4, nullptr, nullptr, nullptr, sA, t, n);
    agg_kernel<60, 60, true><<<1024, 256>>>(rp, meta, t, dis, b4, bufB, sA, n);
    // L5: 60->70
    gemm_kernel<60, 60, 70, 72, true, true><<<gb, 256>>>(bufB, W5, g3, be3, sA, sB, t, n);
    agg_kernel<70, 72, true><<<1024, 256>>>(rp, meta, t, dis, b5, bufA, sB, n);
    // L6: 70->88 -> out
    gemm_kernel<70, 72, 88, 88, true, false><<<gb, 256>>>(bufA, W6, g4, be4, sB, nullptr, t, n);
    agg_kernel<88, 88, false><<<1024, 256>>>(rp, meta, t, dis, b6, out, nullptr, n);
}